// round 11
// baseline (speedup 1.0000x reference)
#include <cuda_runtime.h>
#include <cuda_bf16.h>
#include <math.h>

// ---------------------------------------------------------------------------
// HeteroAttention R11: R10 + kernel merging (prep = pack_x|pack_qa|combine_w,
// proj = kv|q) + attn __launch_bounds__(256,2) for 2 CTAs/SM.
// Math identical to R5..R10 (bf16 hi/lo, 3-term MMA).
// ---------------------------------------------------------------------------

#define NKEY  294
#define SCALE 0.17677669529663687f

// ---------------- scratch ----------------------------------------------------
__device__ __nv_bfloat16 g_Xh[19267584];     // [bz*3136+t][256]
__device__ __nv_bfloat16 g_Xl[19267584];
__device__ __nv_bfloat16 g_Wkvh[24*512*256]; // [bz][o(512)][d]
__device__ __nv_bfloat16 g_Wkvl[24*512*256];
__device__ float         g_bKV [24*512];
__device__ __nv_bfloat16 g_WQh[2*65536];
__device__ __nv_bfloat16 g_WQl[2*65536];
__device__ __nv_bfloat16 g_WAh[2*65536];
__device__ __nv_bfloat16 g_WAl[2*65536];
__device__ __nv_bfloat16 g_Kh[2048*9408];    // [bh][n(294)][p(32)]
__device__ __nv_bfloat16 g_Kl[2048*9408];
__device__ __nv_bfloat16 g_Vth[2048*9728];   // [bh][p(32)][n(304)] pad cols zero
__device__ __nv_bfloat16 g_Vtl[2048*9728];
__device__ __nv_bfloat16 g_Qh[2048*1568];    // [bh][a(49)][p(32)]
__device__ __nv_bfloat16 g_Ql[2048*1568];
__device__ __nv_bfloat16 g_AOh[256*12544];   // [bxy*49+a][256]
__device__ __nv_bfloat16 g_AOl[256*12544];

// ---------------- helpers -----------------------------------------------------
__device__ __forceinline__ unsigned pk(__nv_bfloat16 a, __nv_bfloat16 b) {
    __nv_bfloat162 t = __halves2bfloat162(a, b);
    return *reinterpret_cast<unsigned*>(&t);
}
__device__ __forceinline__ void split4(float4 f, uint2& h, uint2& l) {
    __nv_bfloat16 h0 = __float2bfloat16_rn(f.x), h1 = __float2bfloat16_rn(f.y);
    __nv_bfloat16 h2 = __float2bfloat16_rn(f.z), h3 = __float2bfloat16_rn(f.w);
    __nv_bfloat16 l0 = __float2bfloat16_rn(f.x - __bfloat162float(h0));
    __nv_bfloat16 l1 = __float2bfloat16_rn(f.y - __bfloat162float(h1));
    __nv_bfloat16 l2 = __float2bfloat16_rn(f.z - __bfloat162float(h2));
    __nv_bfloat16 l3 = __float2bfloat16_rn(f.w - __bfloat162float(h3));
    h.x = pk(h0, h1); h.y = pk(h2, h3);
    l.x = pk(l0, l1); l.y = pk(l2, l3);
}
__device__ __forceinline__ void mma_bf16(float* c, unsigned a0, unsigned a1,
                                         unsigned a2, unsigned a3,
                                         unsigned b0, unsigned b1) {
    asm volatile(
        "mma.sync.aligned.m16n8k16.row.col.f32.bf16.bf16.f32 "
        "{%0,%1,%2,%3}, {%4,%5,%6,%7}, {%8,%9}, {%0,%1,%2,%3};\n"
        : "+f"(c[0]), "+f"(c[1]), "+f"(c[2]), "+f"(c[3])
        : "r"(a0), "r"(a1), "r"(a2), "r"(a3), "r"(b0), "r"(b1));
}
__device__ __forceinline__ void mma8_bf16(float* c, unsigned a0, unsigned a1,
                                          unsigned b0) {
    asm volatile(
        "mma.sync.aligned.m16n8k8.row.col.f32.bf16.bf16.f32 "
        "{%0,%1,%2,%3}, {%4,%5}, {%6}, {%0,%1,%2,%3};\n"
        : "+f"(c[0]), "+f"(c[1]), "+f"(c[2]), "+f"(c[3])
        : "r"(a0), "r"(a1), "r"(b0));
}
__device__ __forceinline__ void ldsm4(unsigned& r0, unsigned& r1,
                                      unsigned& r2, unsigned& r3, const void* p) {
    unsigned a = (unsigned)__cvta_generic_to_shared(p);
    asm volatile("ldmatrix.sync.aligned.m8n8.x4.shared.b16 {%0,%1,%2,%3}, [%4];\n"
                 : "=r"(r0), "=r"(r1), "=r"(r2), "=r"(r3) : "r"(a));
}
__device__ __forceinline__ void ldsm2(unsigned& r0, unsigned& r1, const void* p) {
    unsigned a = (unsigned)__cvta_generic_to_shared(p);
    asm volatile("ldmatrix.sync.aligned.m8n8.x2.shared.b16 {%0,%1}, [%2];\n"
                 : "=r"(r0), "=r"(r1) : "r"(a));
}
__device__ __forceinline__ void cpa16(void* dst, const void* src) {
    unsigned d = (unsigned)__cvta_generic_to_shared(dst);
    asm volatile("cp.async.cg.shared.global [%0], [%1], 16;\n" :: "r"(d), "l"(src));
}
__device__ __forceinline__ void cpa_commit() { asm volatile("cp.async.commit_group;\n"); }
__device__ __forceinline__ int swz(int row, int seg) {
    return row * 32 + ((seg ^ ((row >> 1) & 3)) << 3);
}

// ---------------- merged prep kernel ------------------------------------------
// grid = 18816 (pack_x) + 128 (pack_qa) + 192 (combine_w)
__global__ void __launch_bounds__(256) prep_kernel(
        const float4* __restrict__ x,
        const float* __restrict__ Wq, const float* __restrict__ Wa,
        const float* __restrict__ Wk, const float* __restrict__ bk,
        const float* __restrict__ Wv, const float* __restrict__ bv,
        const float* __restrict__ ratt, const float* __restrict__ rmsg,
        const int* __restrict__ mode) {
    __shared__ float att_s[32 * 33];
    __shared__ float msg_s[32 * 33];
    __shared__ float w_s[32 * 256];
    int blk = blockIdx.x;
    int tid = threadIdx.x;

    if (blk < 18816) {               // ---- pack_x ----
        int i = blk * 256 + tid;
        float4 f = x[i];
        uint2 h, l; split4(f, h, l);
        reinterpret_cast<uint2*>(g_Xh)[i] = h;
        reinterpret_cast<uint2*>(g_Xl)[i] = l;
        return;
    }
    if (blk < 18944) {               // ---- pack_qa ----
        int i = (blk - 18816) * 256 + tid;
        uint2 h, l;
        float4 fq = reinterpret_cast<const float4*>(Wq)[i];
        split4(fq, h, l);
        reinterpret_cast<uint2*>(g_WQh)[i] = h;
        reinterpret_cast<uint2*>(g_WQl)[i] = l;
        float4 fa = reinterpret_cast<const float4*>(Wa)[i];
        split4(fa, h, l);
        reinterpret_cast<uint2*>(g_WAh)[i] = h;
        reinterpret_cast<uint2*>(g_WAl)[i] = l;
        return;
    }
    // ---- combine_w ----
    int cb = blk - 18944;            // 0..191
    int bz = cb >> 3, h = cb & 7;
    int b = bz / 6, z = bz - b * 6;
    int t   = mode[b * 6 + z];
    int rel = mode[b * 6] * 2 + t;

    for (int i = tid; i < 1024; i += 256) {
        int p = i >> 5, q = i & 31;
        att_s[p * 33 + q] = ratt[((rel * 8 + h) * 32 + p) * 32 + q];
        msg_s[p * 33 + q] = rmsg[((rel * 8 + h) * 32 + p) * 32 + q];
    }
    const float* WkB = Wk + (t * 256 + h * 32) * 256;
    for (int i = tid; i < 8192; i += 256) w_s[i] = WkB[i];
    __syncthreads();
    {
        int p = tid & 31;
        for (int d = tid >> 5; d < 256; d += 8) {
            float acc = 0.f;
            #pragma unroll
            for (int q = 0; q < 32; q++) acc = fmaf(att_s[p * 33 + q], w_s[q * 256 + d], acc);
            size_t idx = (size_t)bz * 131072 + (size_t)(h * 32 + p) * 256 + d;
            __nv_bfloat16 hv = __float2bfloat16_rn(acc);
            g_Wkvh[idx] = hv;
            g_Wkvl[idx] = __float2bfloat16_rn(acc - __bfloat162float(hv));
        }
        if (tid < 32) {
            float acc = 0.f;
            #pragma unroll
            for (int q = 0; q < 32; q++) acc = fmaf(att_s[tid * 33 + q], bk[t * 256 + h * 32 + q], acc);
            g_bKV[bz * 512 + h * 32 + tid] = acc;
        }
    }
    __syncthreads();
    const float* WvB = Wv + (t * 256 + h * 32) * 256;
    for (int i = tid; i < 8192; i += 256) w_s[i] = WvB[i];
    __syncthreads();
    {
        int qo = tid & 31;
        for (int d = tid >> 5; d < 256; d += 8) {
            float acc = 0.f;
            #pragma unroll
            for (int p = 0; p < 32; p++) acc = fmaf(msg_s[p * 33 + qo], w_s[p * 256 + d], acc);
            size_t idx = (size_t)bz * 131072 + (size_t)(256 + h * 32 + qo) * 256 + d;
            __nv_bfloat16 hv = __float2bfloat16_rn(acc);
            g_Wkvh[idx] = hv;
            g_Wkvl[idx] = __float2bfloat16_rn(acc - __bfloat162float(hv));
        }
        if (tid < 32) {
            float acc = 0.f;
            #pragma unroll
            for (int p = 0; p < 32; p++) acc = fmaf(msg_s[p * 33 + tid], bv[t * 256 + h * 32 + p], acc);
            g_bKV[bz * 512 + 256 + h * 32 + tid] = acc;
        }
    }
}

// ---------------- 64x128x256 tensor-core tile (swizzled smem) ------------------
__device__ __forceinline__ void load_chunk(char* sm, int buf,
        const __nv_bfloat16* __restrict__ Ah, const __nv_bfloat16* __restrict__ Al,
        const __nv_bfloat16* __restrict__ Bh, const __nv_bfloat16* __restrict__ Bl,
        int kc) {
    int tid = threadIdx.x;
    {   // A: 64 rows x 4 segs
        int r = tid >> 2, s = tid & 3;
        int dst = r * 64 + ((s ^ ((r >> 1) & 3)) << 4);
        int go = r * 256 + kc + s * 8;
        cpa16(sm + buf * 4096 + dst, Ah + go);
        cpa16(sm + 8192 + buf * 4096 + dst, Al + go);
    }
    #pragma unroll
    for (int i = 0; i < 2; i++) {   // B: 128 rows x 4 segs
        int id = tid + i * 256;
        int r = id >> 2, s = id & 3;
        int dst = r * 64 + ((s ^ ((r >> 1) & 3)) << 4);
        int go = r * 256 + kc + s * 8;
        cpa16(sm + 16384 + buf * 8192 + dst, Bh + go);
        cpa16(sm + 32768 + buf * 8192 + dst, Bl + go);
    }
}

__device__ __forceinline__ void gemm_tile(
        const __nv_bfloat16* __restrict__ Ah, const __nv_bfloat16* __restrict__ Al,
        const __nv_bfloat16* __restrict__ Bh, const __nv_bfloat16* __restrict__ Bl,
        float acc[8][4], char* sm) {
    int tid = threadIdx.x;
    int warp = tid >> 5, lane = tid & 31;
    int wm = warp >> 1, wn = warp & 1;
    int lrow = lane & 15, lseg = lane >> 4;

    load_chunk(sm, 0, Ah, Al, Bh, Bl, 0);
    cpa_commit();

    #pragma unroll 1
    for (int ch = 0; ch < 8; ch++) {
        asm volatile("cp.async.wait_group 0;\n");
        __syncthreads();
        if (ch < 7) {
            load_chunk(sm, (ch + 1) & 1, Ah, Al, Bh, Bl, (ch + 1) * 32);
            cpa_commit();
        }
        int buf = ch & 1;
        const __nv_bfloat16* pAh = (const __nv_bfloat16*)(sm + buf * 4096);
        const __nv_bfloat16* pAl = (const __nv_bfloat16*)(sm + 8192 + buf * 4096);
        const __nv_bfloat16* pBh = (const __nv_bfloat16*)(sm + 16384 + buf * 8192);
        const __nv_bfloat16* pBl = (const __nv_bfloat16*)(sm + 32768 + buf * 8192);
        #pragma unroll
        for (int ks = 0; ks < 32; ks += 16) {
            int sa = (ks >> 3) + lseg;
            unsigned ah0, ah1, ah2, ah3, al0, al1, al2, al3;
            int ar = wm * 16 + lrow;
            int aoff = swz(ar, sa);
            ldsm4(ah0, ah1, ah2, ah3, pAh + aoff);
            ldsm4(al0, al1, al2, al3, pAl + aoff);
            #pragma unroll
            for (int t = 0; t < 4; t++) {
                unsigned bh0, bh1, bh2, bh3, bl0, bl1, bl2, bl3;
                int br = wn * 64 + t * 16 + lrow;
                int boff = swz(br, sa);
                ldsm4(bh0, bh1, bh2, bh3, pBh + boff);
                ldsm4(bl0, bl1, bl2, bl3, pBl + boff);
                mma_bf16(acc[2 * t],     ah0, ah1, ah2, ah3, bh0, bh2);
                mma_bf16(acc[2 * t],     ah0, ah1, ah2, ah3, bl0, bl2);
                mma_bf16(acc[2 * t],     al0, al1, al2, al3, bh0, bh2);
                mma_bf16(acc[2 * t + 1], ah0, ah1, ah2, ah3, bh1, bh3);
                mma_bf16(acc[2 * t + 1], ah0, ah1, ah2, ah3, bl1, bl3);
                mma_bf16(acc[2 * t + 1], al0, al1, al2, al3, bh1, bh3);
            }
        }
    }
}

// ---------------- merged projection kernel: kv (0..4703) | q (4704..5095) ------
__global__ void __launch_bounds__(256, 4) proj_mma(const int* __restrict__ mode,
                                                   const float* __restrict__ bq) {
    extern __shared__ char sm[];
    int blk = blockIdx.x;
    int warp = threadIdx.x >> 5, lane = threadIdx.x & 31;
    int wm = warp >> 1, wn = warp & 1;
    int gid = lane >> 2, tg = lane & 3;

    if (blk < 4704) {   // ---- K'/V' projection ----
        int bz = blk / 196; int r = blk - bz * 196;
        int mt = r >> 2, nt = r & 3;
        int b = bz / 6, z = bz - b * 6;
        const __nv_bfloat16* Ah = g_Xh + (size_t)(bz * 3136 + mt * 64) * 256;
        const __nv_bfloat16* Al = g_Xl + (size_t)(bz * 3136 + mt * 64) * 256;
        const __nv_bfloat16* Bh = g_Wkvh + (size_t)bz * 131072 + (size_t)nt * 128 * 256;
        const __nv_bfloat16* Bl = g_Wkvl + (size_t)bz * 131072 + (size_t)nt * 128 * 256;
        float acc[8][4] = {};
        gemm_tile(Ah, Al, Bh, Bl, acc, sm);

        #pragma unroll
        for (int j = 0; j < 8; j++) {
            #pragma unroll
            for (int ee = 0; ee < 2; ee++) {
                int row = mt * 64 + wm * 16 + gid + ee * 8;
                int o0 = nt * 128 + wn * 64 + j * 8 + tg * 2;
                float v0 = acc[j][ee * 2]     + g_bKV[bz * 512 + o0];
                float v1 = acc[j][ee * 2 + 1] + g_bKV[bz * 512 + o0 + 1];
                int od = o0 & 255;
                int xy = row / 49, ef = row - xy * 49;
                int hh = od >> 5, p = od & 31;
                size_t bh = (size_t)((b * 64 + xy) * 8 + hh);
                __nv_bfloat16 h0 = __float2bfloat16_rn(v0);
                __nv_bfloat16 h1 = __float2bfloat16_rn(v1);
                __nv_bfloat16 l0 = __float2bfloat16_rn(v0 - __bfloat162float(h0));
                __nv_bfloat16 l1 = __float2bfloat16_rn(v1 - __bfloat162float(h1));
                if (o0 < 256) {
                    size_t idx = bh * 9408 + (size_t)(z * 49 + ef) * 32 + p;
                    *reinterpret_cast<__nv_bfloat162*>(g_Kh + idx) = __halves2bfloat162(h0, h1);
                    *reinterpret_cast<__nv_bfloat162*>(g_Kl + idx) = __halves2bfloat162(l0, l1);
                } else {
                    size_t idx = bh * 9728 + (size_t)p * 304 + z * 49 + ef;
                    g_Vth[idx] = h0; g_Vtl[idx] = l0;
                    g_Vth[idx + 304] = h1; g_Vtl[idx + 304] = l1;
                }
            }
        }
    } else {            // ---- Q projection ----
        int qb = blk - 4704;
        int b = qb / 98; int r = qb - b * 98;
        int mt = r >> 1, nt = r & 1;
        int tq = mode[b * 6];
        const __nv_bfloat16* Ah = g_Xh + (size_t)(b * 6 * 3136 + mt * 64) * 256;
        const __nv_bfloat16* Al = g_Xl + (size_t)(b * 6 * 3136 + mt * 64) * 256;
        const __nv_bfloat16* Bh = g_WQh + (size_t)tq * 65536 + (size_t)nt * 128 * 256;
        const __nv_bfloat16* Bl = g_WQl + (size_t)tq * 65536 + (size_t)nt * 128 * 256;
        float acc[8][4] = {};
        gemm_tile(Ah, Al, Bh, Bl, acc, sm);

        #pragma unroll
        for (int j = 0; j < 8; j++) {
            #pragma unroll
            for (int ee = 0; ee < 2; ee++) {
                int row = mt * 64 + wm * 16 + gid + ee * 8;
                int o0 = nt * 128 + wn * 64 + j * 8 + tg * 2;
                float v0 = (acc[j][ee * 2]     + bq[tq * 256 + o0])     * SCALE;
                float v1 = (acc[j][ee * 2 + 1] + bq[tq * 256 + o0 + 1]) * SCALE;
                int xy = row / 49, a = row - xy * 49;
                int hh = o0 >> 5, p = o0 & 31;
                size_t idx = (size_t)((b * 64 + xy) * 8 + hh) * 1568 + a * 32 + p;
                __nv_bfloat16 h0 = __float2bfloat16_rn(v0);
                __nv_bfloat16 h1 = __float2bfloat16_rn(v1);
                *reinterpret_cast<__nv_bfloat162*>(g_Qh + idx) = __halves2bfloat162(h0, h1);
                *reinterpret_cast<__nv_bfloat162*>(g_Ql + idx) = __halves2bfloat162(
                    __float2bfloat16_rn(v0 - __bfloat162float(h0)),
                    __float2bfloat16_rn(v1 - __bfloat162float(h1)));
            }
        }
    }
}

// ---------------- K3: tensor-core attention ------------------------------------
#define SM_VTH   0
#define SM_VTL   20992
#define SM_WRED  41984
#define SM_KH    44032
#define SM_KL    64512
#define SM_QH    84992
#define SM_QL    89088
#define SM_BIAS  93184
#define SM_RED   44032
#define SM_TOTAL 111616
#define VSTR 328

__global__ void __launch_bounds__(256, 2) attn_kernel(const float* __restrict__ pos_table) {
    extern __shared__ char sm[];
    int bh = blockIdx.x;
    int h = bh & 7, bxy = bh >> 3;
    int tid = threadIdx.x;
    int w = tid >> 5, lane = tid & 31;
    int gid = lane >> 2, tg = lane & 3;
    int lrow = lane & 15, lseg = lane >> 4;
    float* biasS = (float*)(sm + SM_BIAS);
    float* wred  = (float*)(sm + SM_WRED);

    const __nv_bfloat16* Kg_h = g_Kh + (size_t)bh * 9408;
    const __nv_bfloat16* Kg_l = g_Kl + (size_t)bh * 9408;
    const __nv_bfloat16* Vg_h = g_Vth + (size_t)bh * 9728;
    const __nv_bfloat16* Vg_l = g_Vtl + (size_t)bh * 9728;
    const __nv_bfloat16* Qg_h = g_Qh + (size_t)bh * 1568;
    const __nv_bfloat16* Qg_l = g_Ql + (size_t)bh * 1568;

    for (int i = tid; i < 240; i += 256) {
        int r = 49 + i / 16, c = i % 16;
        ((unsigned*)(sm + SM_QH))[r * 16 + c] = 0;
        ((unsigned*)(sm + SM_QL))[r * 16 + c] = 0;
    }
    {
        int r = tid >> 3, c = tid & 7;
        ((unsigned*)(sm + SM_VTH))[r * 164 + 152 + c] = 0;
        ((unsigned*)(sm + SM_VTL))[r * 164 + 152 + c] = 0;
    }
    for (int i = tid; i < 1176; i += 256) {
        int r = i >> 2, s = i & 3;
        int dst = r * 64 + ((s ^ ((r >> 1) & 3)) << 4);
        cpa16(sm + SM_KH + dst, Kg_h + r * 32 + s * 8);
        cpa16(sm + SM_KL + dst, Kg_l + r * 32 + s * 8);
    }
    for (int i = tid; i < 1216; i += 256) {
        int r = i / 38, seg = i - r * 38;
        cpa16(sm + SM_VTH + r * 656 + seg * 16, Vg_h + r * 304 + seg * 8);
        cpa16(sm + SM_VTL + r * 656 + seg * 16, Vg_l + r * 304 + seg * 8);
    }
    for (int i = tid; i < 196; i += 256) {
        int r = i >> 2, s = i & 3;
        int dst = r * 64 + ((s ^ ((r >> 1) & 3)) << 4);
        cpa16(sm + SM_QH + dst, Qg_h + r * 32 + s * 8);
        cpa16(sm + SM_QL + dst, Qg_l + r * 32 + s * 8);
    }
    cpa_commit();
    for (int i = tid; i < 2401; i += 256) {
        int a = i / 49, ef = i - a * 49;
        int au = a / 7, av = a - au * 7, eu = ef / 7, ev = ef - eu * 7;
        int idx = (au - eu + 6) * 13 + (av - ev + 6);
        biasS[i] = pos_table[idx * 8 + h];
    }
    asm volatile("cp.async.wait_group 0;\n");
    __syncthreads();

    const __nv_bfloat16* Qs_h = (const __nv_bfloat16*)(sm + SM_QH);
    const __nv_bfloat16* Qs_l = (const __nv_bfloat16*)(sm + SM_QL);
    const __nv_bfloat16* Ks_h = (const __nv_bfloat16*)(sm + SM_KH);
    const __nv_bfloat16* Ks_l = (const __nv_bfloat16*)(sm + SM_KL);
    int nb = w * 40;

    float acc[4][5][4];
    #pragma unroll
    for (int mt = 0; mt < 4; mt++)
        #pragma unroll
        for (int j = 0; j < 5; j++)
            #pragma unroll
            for (int e = 0; e < 4; e++) acc[mt][j][e] = 0.f;

    #pragma unroll
    for (int ks = 0; ks < 32; ks += 16) {
        int sa = (ks >> 3) + lseg;
        unsigned ah[4][4], al[4][4];
        #pragma unroll
        for (int mt = 0; mt < 4; mt++) {
            int ar = mt * 16 + lrow;
            int aoff = swz(ar, sa);
            ldsm4(ah[mt][0], ah[mt][1], ah[mt][2], ah[mt][3], Qs_h + aoff);
            ldsm4(al[mt][0], al[mt][1], al[mt][2], al[mt][3], Qs_l + aoff);
        }
        unsigned bhf[5][2], blf[5][2];
        #pragma unroll
        for (int jp = 0; jp < 2; jp++) {
            unsigned r0, r1, r2, r3;
            int br = nb + jp * 16 + lrow;
            int boff = swz(br, sa);
            ldsm4(r0, r1, r2, r3, Ks_h + boff);
            bhf[2 * jp][0] = r0; bhf[2 * jp][1] = r2;
            bhf[2 * jp + 1][0] = r1; bhf[2 * jp + 1][1] = r3;
            ldsm4(r0, r1, r2, r3, Ks_l + boff);
            blf[2 * jp][0] = r0; blf[2 * jp][1] = r2;
            blf[2 * jp + 1][0] = r1; blf[2 * jp + 1][1] = r3;
        }
        {
            unsigned r0, r1;
            int l = lane & 15;
            int br = nb + 32 + (l & 7);
            int sg = (ks >> 3) + (l >> 3);
            int boff = swz(br, sg);
            ldsm2(r0, r1, Ks_h + boff);
            bhf[4][0] = r0; bhf[4][1] = r1;
            ldsm2(r0, r1, Ks_l + boff);
            blf[4][0] = r0; blf[4][1] = r1;
        }
        #pragma unroll
        for (int mt = 0; mt < 4; mt++)
            #pragma unroll
            for (int j = 0; j < 5; j++) {
                mma_bf16(acc[mt][j], ah[mt][0], ah[mt][1], ah[mt][2], ah[mt][3], bhf[j][0], bhf[j][1]);
                mma_bf16(acc[mt][j], ah[mt][0], ah[mt][1], ah[mt][2], ah[mt][3], blf[j][0], blf[j][1]);
                mma_bf16(acc[mt][j], al[mt][0], al[mt][1], al[mt][2], al[mt][3], bhf[j][0], bhf[j][1]);
            }
    }

    int ef_[5][2]; bool val_[5][2];
    #pragma unroll
    for (int j = 0; j < 5; j++)
        #pragma unroll
        for (int c = 0; c < 2; c++) {
            int n = nb + j * 8 + tg * 2 + c;
            val_[j][c] = (n < NKEY);
            ef_[j][c] = n % 49;
        }
    #pragma unroll
    for (int mt = 0; mt < 4; mt++)
        #pragma unroll
        for (int half = 0; half < 2; half++) {
            int row = mt * 16 + gid + half * 8;
            #pragma unroll
            for (int j = 0; j < 5; j++)
                #pragma unroll
                for (int c = 0; c < 2; c++) {
                    float& a = acc[mt][j][half * 2 + c];
                    if (!val_[j][c]) a = -1e30f;
                    else if (row < 49) a += biasS[row * 49 + ef_[j][c]];
                }
        }

    float gmax[4][2];
    #pragma unroll
    for (int mt = 0; mt < 4; mt++)
        #pragma unroll
        for (int half = 0; half < 2; half++) {
            float m = -1e30f;
            #pragma unroll
            for (int j = 0; j < 5; j++) {
                m = fmaxf(m, acc[mt][j][half * 2]);
                m = fmaxf(m, acc[mt][j][half * 2 + 1]);
            }
            m = fmaxf(m, __shfl_xor_sync(0xffffffffu, m, 1));
            m = fmaxf(m, __shfl_xor_sync(0xffffffffu, m, 2));
            if (tg == 0) wred[(mt * 16 + gid + half * 8) * 8 + w] = m;
        }
    __syncthreads();
    #pragma unroll
    for (int mt = 0; mt < 4; mt++)
        #pragma unroll
        for (int half = 0; half < 2; half++) {
            int row = mt * 16 + gid + half * 8;
            float g = wred[row * 8];
            #pragma unroll
            for (int k = 1; k < 8; k++) g = fmaxf(g, wred[row * 8 + k]);
            gmax[mt][half] = g;
        }
    __syncthreads();
    float ginv[4][2];
    #pragma unroll
    for (int mt = 0; mt < 4; mt++)
        #pragma unroll
        for (int half = 0; half < 2; half++) {
            float s = 0.f;
            #pragma unroll
            for (int j = 0; j < 5; j++) {
                float e0 = __expf(acc[mt][j][half * 2]     - gmax[mt][half]);
                float e1 = __expf(acc[mt][j][half * 2 + 1] - gmax[mt][half]);
                acc[mt][j][half * 2] = e0; acc[mt][j][half * 2 + 1] = e1;
                s += e0 + e1;
            }
            s += __shfl_xor_sync(0xffffffffu, s, 1);
            s += __shfl_xor_sync(0xffffffffu, s, 2);
            if (tg == 0) wred[(mt * 16 + gid + half * 8) * 8 + w] = s;
        }
    __syncthreads();
    #pragma unroll
    for (int mt = 0; mt < 4; mt++)
        #pragma unroll
        for (int half = 0; half < 2; half++) {
            int row = mt * 16 + gid + half * 8;
            float s = 0.f;
            #pragma unroll
            for (int k = 0; k < 8; k++) s += wred[row * 8 + k];
            ginv[mt][half] = 1.f / s;
        }

    unsigned ph[4][5][2], pl[4][5][2];
    #pragma unroll
    for (int mt = 0; mt < 4; mt++)
        #pragma unroll
        for (int j = 0; j < 5; j++) {
            float p0 = acc[mt][j][0] * ginv[mt][0];
            float p1 = acc[mt][j][1] * ginv[mt][0];
            float p2 = acc[mt][j][2] * ginv[mt][1];
            float p3 = acc[mt][j][3] * ginv[mt][1];
            __nv_bfloat16 h0 = __float2bfloat16_rn(p0), h1 = __float2bfloat16_rn(p1);
            __nv_bfloat16 h2 = __float2bfloat16_rn(p2), h3 = __float2bfloat16_rn(p3);
            ph[mt][j][0] = pk(h0, h1); ph[mt][j][1] = pk(h2, h3);
            pl[mt][j][0] = pk(__float2bfloat16_rn(p0 - __bfloat162float(h0)),
                              __float2bfloat16_rn(p1 - __bfloat162float(h1)));
            pl[mt][j][1] = pk(__float2bfloat16_rn(p2 - __bfloat162float(h2)),
                              __float2bfloat16_rn(p3 - __bfloat162float(h3)));
        }

    const __nv_bfloat16* Vt_h = (const __nv_bfloat16*)(sm + SM_VTH);
    const __nv_bfloat16* Vt_l = (const __nv_bfloat16*)(sm + SM_VTL);
    float cc[4][4][4];
    #pragma unroll
    for (int mt = 0; mt < 4; mt++)
        #pragma unroll
        for (int nt = 0; nt < 4; nt++)
            #pragma unroll
            for (int e = 0; e < 4; e++) cc[mt][nt][e] = 0.f;

    int lcol8 = lseg << 3;
    #pragma unroll
    for (int t = 0; t < 2; t++) {
        int kb = w * 40 + t * 16;
        unsigned vh[4][2], vl[4][2];
        #pragma unroll
        for (int g = 0; g < 2; g++) {
            unsigned r0, r1, r2, r3;
            int voff = (g * 16 + lrow) * VSTR + kb + lcol8;
            ldsm4(r0, r1, r2, r3, Vt_h + voff);
            vh[2 * g][0] = r0; vh[2 * g][1] = r2;
            vh[2 * g + 1][0] = r1; vh[2 * g + 1][1] = r3;
            ldsm4(r0, r1, r2, r3, Vt_l + voff);
            vl[2 * g][0] = r0; vl[2 * g][1] = r2;
            vl[2 * g + 1][0] = r1; vl[2 * g + 1][1] = r3;
        }
        #pragma unroll
        for (int mt = 0; mt < 4; mt++) {
            unsigned a0 = ph[mt][2 * t][0], a1 = ph[mt][2 * t][1];
            unsigned a2 = ph[mt][2 * t + 1][0], a3 = ph[mt][2 * t + 1][1];
            unsigned b0 = pl[mt][2 * t][0], b1 = pl[mt][2 * t][1];
            unsigned b2 = pl[mt][2 * t + 1][0], b3 = pl[mt][2 * t + 1][1];
            #pragma unroll
            for (int nt = 0; nt < 4; nt++) {
                mma_bf16(cc[mt][nt], a0, a1, a2, a3, vh[nt][0], vh[nt][1]);
                mma_bf16(cc[mt][nt], a0, a1, a2, a3, vl[nt][0], vl[nt][1]);
                mma_bf16(cc[mt][nt], b0, b1, b2, b3, vh[nt][0], vh[nt][1]);
            }
        }
    }
    {
        int kb = w * 40 + 32;
        unsigned v8h[4], v8l[4];
        #pragma unroll
        for (int g = 0; g < 2; g++) {
            unsigned r0, r1;
            int voff = (g * 16 + lrow) * VSTR + kb;
            ldsm2(r0, r1, Vt_h + voff);
            v8h[2 * g] = r0; v8h[2 * g + 1] = r1;
            ldsm2(r0, r1, Vt_l + voff);
            v8l[2 * g] = r0; v8l[2 * g + 1] = r1;
        }
        #pragma unroll
        for (int mt = 0; mt < 4; mt++) {
            unsigned a0 = ph[mt][4][0], a1 = ph[mt][4][1];
            unsigned b0 = pl[mt][4][0], b1 = pl[mt][4][1];
            #pragma unroll
            for (int nt = 0; nt < 4; nt++) {
                mma8_bf16(cc[mt][nt], a0, a1, v8h[nt]);
                mma8_bf16(cc[mt][nt], a0, a1, v8l[nt]);
                mma8_bf16(cc[mt][nt], b0, b1, v8h[nt]);
            }
        }
    }

    float* red = (float*)(sm + SM_RED);
    __syncthreads();
    #pragma unroll
    for (int mt = 0; mt < 4; mt++)
        #pragma unroll
        for (int nt = 0; nt < 4; nt++)
            #pragma unroll
            for (int e = 0; e < 4; e++) {
                int row = mt * 16 + gid + ((e >> 1) << 3);
                int p = nt * 8 + tg * 2 + (e & 1);
                red[w * 2112 + row * 33 + p] = cc[mt][nt][e];
            }
    __syncthreads();
    for (int i = tid; i < 2048; i += 256) {
        int row = i >> 5, p = i & 31;
        if (row >= 49) continue;
        float s = 0.f;
        #pragma unroll
        for (int k = 0; k < 8; k++) s += red[k * 2112 + row * 33 + p];
        size_t base = (size_t)(bxy * 49 + row) * 256 + h * 32 + p;
        __nv_bfloat16 hv = __float2bfloat16_rn(s);
        g_AOh[base] = hv;
        g_AOl[base] = __float2bfloat16_rn(s - __bfloat162float(hv));
    }
}

// ---------------- K4: final projection -----------------------------------------
__global__ void __launch_bounds__(256, 4) ao_mma(const int* __restrict__ mode,
                                                 const float* __restrict__ ba,
                                                 float* __restrict__ out) {
    extern __shared__ char sm[];
    int blk = blockIdx.x;
    int b = blk / 98; int r = blk - b * 98;
    int mt = r >> 1, nt = r & 1;
    int ta = mode[b * 6];
    const __nv_bfloat16* Ah = g_AOh + (size_t)(b * 3136 + mt * 64) * 256;
    const __nv_bfloat16* Al = g_AOl + (size_t)(b * 3136 + mt * 64) * 256;
    const __nv_bfloat16* Bh = g_WAh + (size_t)ta * 65536 + (size_t)nt * 128 * 256;
    const __nv_bfloat16* Bl = g_WAl + (size_t)ta * 65536 + (size_t)nt * 128 * 256;
    float acc[8][4] = {};
    gemm_tile(Ah, Al, Bh, Bl, acc, sm);

    int warp = threadIdx.x >> 5, lane = threadIdx.x & 31;
    int wm = warp >> 1, wn = warp & 1;
    int gid = lane >> 2, tg = lane & 3;
    #pragma unroll
    for (int j = 0; j < 8; j++) {
        #pragma unroll
        for (int ee = 0; ee < 2; ee++) {
            int row = mt * 64 + wm * 16 + gid + ee * 8;
            int o0 = nt * 128 + wn * 64 + j * 8 + tg * 2;
            float2 v;
            v.x = acc[j][ee * 2]     + ba[ta * 256 + o0];
            v.y = acc[j][ee * 2 + 1] + ba[ta * 256 + o0 + 1];
            *reinterpret_cast<float2*>(out + (size_t)(b * 3136 + row) * 256 + o0) = v;
        }
    }
}

// ---------------- launch --------------------------------------------------------
extern "C" void kernel_launch(void* const* d_in, const int* in_sizes, int n_in,
                              void* d_out, int out_size) {
    const float* x    = (const float*)d_in[0];
    const int*   mode = (const int*)  d_in[1];
    const float* Wq   = (const float*)d_in[2];
    const float* bq   = (const float*)d_in[3];
    const float* Wk   = (const float*)d_in[4];
    const float* bk   = (const float*)d_in[5];
    const float* Wv   = (const float*)d_in[6];
    const float* bv   = (const float*)d_in[7];
    const float* Wa   = (const float*)d_in[8];
    const float* ba   = (const float*)d_in[9];
    const float* ratt = (const float*)d_in[10];
    const float* rmsg = (const float*)d_in[11];
    const float* post = (const float*)d_in[12];
    float* out = (float*)d_out;

    cudaFuncSetAttribute(attn_kernel, cudaFuncAttributeMaxDynamicSharedMemorySize, SM_TOTAL);
    cudaFuncSetAttribute(proj_mma, cudaFuncAttributeMaxDynamicSharedMemorySize, 49152);
    cudaFuncSetAttribute(ao_mma,   cudaFuncAttributeMaxDynamicSharedMemorySize, 49152);

    prep_kernel<<<19136, 256>>>(reinterpret_cast<const float4*>(x),
                                Wq, Wa, Wk, bk, Wv, bv, ratt, rmsg, mode);
    proj_mma   <<<5096, 256, 49152>>>(mode, bq);
    attn_kernel<<<2048, 256, SM_TOTAL>>>(post);
    ao_mma     <<<392, 256, 49152>>>(mode, ba, out);
}

// round 13
// speedup vs baseline: 1.1170x; 1.1170x over previous
#include <cuda_runtime.h>
#include <cuda_bf16.h>
#include <math.h>

// ---------------------------------------------------------------------------
// HeteroAttention R12: R10 base (separate prep kernels, unbounded attn regs)
// + kv|q merged into proj_mma (the safe part of R11).
// Math identical to R5..R10 (bf16 hi/lo, 3-term MMA).
// ---------------------------------------------------------------------------

#define NKEY  294
#define SCALE 0.17677669529663687f

// ---------------- scratch ----------------------------------------------------
__device__ __nv_bfloat16 g_Xh[19267584];     // [bz*3136+t][256]
__device__ __nv_bfloat16 g_Xl[19267584];
__device__ __nv_bfloat16 g_Wkvh[24*512*256]; // [bz][o(512)][d]
__device__ __nv_bfloat16 g_Wkvl[24*512*256];
__device__ float         g_bKV [24*512];
__device__ __nv_bfloat16 g_WQh[2*65536];
__device__ __nv_bfloat16 g_WQl[2*65536];
__device__ __nv_bfloat16 g_WAh[2*65536];
__device__ __nv_bfloat16 g_WAl[2*65536];
__device__ __nv_bfloat16 g_Kh[2048*9408];    // [bh][n(294)][p(32)]
__device__ __nv_bfloat16 g_Kl[2048*9408];
__device__ __nv_bfloat16 g_Vth[2048*9728];   // [bh][p(32)][n(304)] pad cols zero
__device__ __nv_bfloat16 g_Vtl[2048*9728];
__device__ __nv_bfloat16 g_Qh[2048*1568];    // [bh][a(49)][p(32)]
__device__ __nv_bfloat16 g_Ql[2048*1568];
__device__ __nv_bfloat16 g_AOh[256*12544];   // [bxy*49+a][256]
__device__ __nv_bfloat16 g_AOl[256*12544];

// ---------------- helpers -----------------------------------------------------
__device__ __forceinline__ unsigned pk(__nv_bfloat16 a, __nv_bfloat16 b) {
    __nv_bfloat162 t = __halves2bfloat162(a, b);
    return *reinterpret_cast<unsigned*>(&t);
}
__device__ __forceinline__ void split4(float4 f, uint2& h, uint2& l) {
    __nv_bfloat16 h0 = __float2bfloat16_rn(f.x), h1 = __float2bfloat16_rn(f.y);
    __nv_bfloat16 h2 = __float2bfloat16_rn(f.z), h3 = __float2bfloat16_rn(f.w);
    __nv_bfloat16 l0 = __float2bfloat16_rn(f.x - __bfloat162float(h0));
    __nv_bfloat16 l1 = __float2bfloat16_rn(f.y - __bfloat162float(h1));
    __nv_bfloat16 l2 = __float2bfloat16_rn(f.z - __bfloat162float(h2));
    __nv_bfloat16 l3 = __float2bfloat16_rn(f.w - __bfloat162float(h3));
    h.x = pk(h0, h1); h.y = pk(h2, h3);
    l.x = pk(l0, l1); l.y = pk(l2, l3);
}
__device__ __forceinline__ void mma_bf16(float* c, unsigned a0, unsigned a1,
                                         unsigned a2, unsigned a3,
                                         unsigned b0, unsigned b1) {
    asm volatile(
        "mma.sync.aligned.m16n8k16.row.col.f32.bf16.bf16.f32 "
        "{%0,%1,%2,%3}, {%4,%5,%6,%7}, {%8,%9}, {%0,%1,%2,%3};\n"
        : "+f"(c[0]), "+f"(c[1]), "+f"(c[2]), "+f"(c[3])
        : "r"(a0), "r"(a1), "r"(a2), "r"(a3), "r"(b0), "r"(b1));
}
__device__ __forceinline__ void mma8_bf16(float* c, unsigned a0, unsigned a1,
                                          unsigned b0) {
    asm volatile(
        "mma.sync.aligned.m16n8k8.row.col.f32.bf16.bf16.f32 "
        "{%0,%1,%2,%3}, {%4,%5}, {%6}, {%0,%1,%2,%3};\n"
        : "+f"(c[0]), "+f"(c[1]), "+f"(c[2]), "+f"(c[3])
        : "r"(a0), "r"(a1), "r"(b0));
}
__device__ __forceinline__ void ldsm4(unsigned& r0, unsigned& r1,
                                      unsigned& r2, unsigned& r3, const void* p) {
    unsigned a = (unsigned)__cvta_generic_to_shared(p);
    asm volatile("ldmatrix.sync.aligned.m8n8.x4.shared.b16 {%0,%1,%2,%3}, [%4];\n"
                 : "=r"(r0), "=r"(r1), "=r"(r2), "=r"(r3) : "r"(a));
}
__device__ __forceinline__ void ldsm2(unsigned& r0, unsigned& r1, const void* p) {
    unsigned a = (unsigned)__cvta_generic_to_shared(p);
    asm volatile("ldmatrix.sync.aligned.m8n8.x2.shared.b16 {%0,%1}, [%2];\n"
                 : "=r"(r0), "=r"(r1) : "r"(a));
}
__device__ __forceinline__ void cpa16(void* dst, const void* src) {
    unsigned d = (unsigned)__cvta_generic_to_shared(dst);
    asm volatile("cp.async.cg.shared.global [%0], [%1], 16;\n" :: "r"(d), "l"(src));
}
__device__ __forceinline__ void cpa_commit() { asm volatile("cp.async.commit_group;\n"); }
__device__ __forceinline__ int swz(int row, int seg) {
    return row * 32 + ((seg ^ ((row >> 1) & 3)) << 3);
}

// ---------------- pack kernels (separate, R10) --------------------------------
__global__ void pack_x(const float4* __restrict__ x) {
    int i = blockIdx.x * 256 + threadIdx.x;
    float4 f = x[i];
    uint2 h, l; split4(f, h, l);
    reinterpret_cast<uint2*>(g_Xh)[i] = h;
    reinterpret_cast<uint2*>(g_Xl)[i] = l;
}
__global__ void pack_qa(const float* __restrict__ Wq, const float* __restrict__ Wa) {
    int i = blockIdx.x * 256 + threadIdx.x;
    uint2 h, l;
    float4 fq = reinterpret_cast<const float4*>(Wq)[i];
    split4(fq, h, l);
    reinterpret_cast<uint2*>(g_WQh)[i] = h;
    reinterpret_cast<uint2*>(g_WQl)[i] = l;
    float4 fa = reinterpret_cast<const float4*>(Wa)[i];
    split4(fa, h, l);
    reinterpret_cast<uint2*>(g_WAh)[i] = h;
    reinterpret_cast<uint2*>(g_WAl)[i] = l;
}

// ---------------- K0b: fold relation matrices --------------------------------
__global__ void combine_w(const float* __restrict__ Wk, const float* __restrict__ bk,
                          const float* __restrict__ Wv, const float* __restrict__ bv,
                          const float* __restrict__ ratt, const float* __restrict__ rmsg,
                          const int* __restrict__ mode) {
    __shared__ float att_s[32 * 33];
    __shared__ float msg_s[32 * 33];
    __shared__ float w_s[32 * 256];
    int bz = blockIdx.x >> 3, h = blockIdx.x & 7;
    int b = bz / 6, z = bz - b * 6;
    int t   = mode[b * 6 + z];
    int rel = mode[b * 6] * 2 + t;
    int tid = threadIdx.x;

    for (int i = tid; i < 1024; i += 256) {
        int p = i >> 5, q = i & 31;
        att_s[p * 33 + q] = ratt[((rel * 8 + h) * 32 + p) * 32 + q];
        msg_s[p * 33 + q] = rmsg[((rel * 8 + h) * 32 + p) * 32 + q];
    }
    const float* WkB = Wk + (t * 256 + h * 32) * 256;
    for (int i = tid; i < 8192; i += 256) w_s[i] = WkB[i];
    __syncthreads();
    {
        int p = tid & 31;
        for (int d = tid >> 5; d < 256; d += 8) {
            float acc = 0.f;
            #pragma unroll
            for (int q = 0; q < 32; q++) acc = fmaf(att_s[p * 33 + q], w_s[q * 256 + d], acc);
            size_t idx = (size_t)bz * 131072 + (size_t)(h * 32 + p) * 256 + d;
            __nv_bfloat16 hv = __float2bfloat16_rn(acc);
            g_Wkvh[idx] = hv;
            g_Wkvl[idx] = __float2bfloat16_rn(acc - __bfloat162float(hv));
        }
        if (tid < 32) {
            float acc = 0.f;
            #pragma unroll
            for (int q = 0; q < 32; q++) acc = fmaf(att_s[tid * 33 + q], bk[t * 256 + h * 32 + q], acc);
            g_bKV[bz * 512 + h * 32 + tid] = acc;
        }
    }
    __syncthreads();
    const float* WvB = Wv + (t * 256 + h * 32) * 256;
    for (int i = tid; i < 8192; i += 256) w_s[i] = WvB[i];
    __syncthreads();
    {
        int qo = tid & 31;
        for (int d = tid >> 5; d < 256; d += 8) {
            float acc = 0.f;
            #pragma unroll
            for (int p = 0; p < 32; p++) acc = fmaf(msg_s[p * 33 + qo], w_s[p * 256 + d], acc);
            size_t idx = (size_t)bz * 131072 + (size_t)(256 + h * 32 + qo) * 256 + d;
            __nv_bfloat16 hv = __float2bfloat16_rn(acc);
            g_Wkvh[idx] = hv;
            g_Wkvl[idx] = __float2bfloat16_rn(acc - __bfloat162float(hv));
        }
        if (tid < 32) {
            float acc = 0.f;
            #pragma unroll
            for (int p = 0; p < 32; p++) acc = fmaf(msg_s[p * 33 + tid], bv[t * 256 + h * 32 + p], acc);
            g_bKV[bz * 512 + 256 + h * 32 + tid] = acc;
        }
    }
}

// ---------------- 64x128x256 tensor-core tile (swizzled smem) ------------------
__device__ __forceinline__ void load_chunk(char* sm, int buf,
        const __nv_bfloat16* __restrict__ Ah, const __nv_bfloat16* __restrict__ Al,
        const __nv_bfloat16* __restrict__ Bh, const __nv_bfloat16* __restrict__ Bl,
        int kc) {
    int tid = threadIdx.x;
    {   // A: 64 rows x 4 segs
        int r = tid >> 2, s = tid & 3;
        int dst = r * 64 + ((s ^ ((r >> 1) & 3)) << 4);
        int go = r * 256 + kc + s * 8;
        cpa16(sm + buf * 4096 + dst, Ah + go);
        cpa16(sm + 8192 + buf * 4096 + dst, Al + go);
    }
    #pragma unroll
    for (int i = 0; i < 2; i++) {   // B: 128 rows x 4 segs
        int id = tid + i * 256;
        int r = id >> 2, s = id & 3;
        int dst = r * 64 + ((s ^ ((r >> 1) & 3)) << 4);
        int go = r * 256 + kc + s * 8;
        cpa16(sm + 16384 + buf * 8192 + dst, Bh + go);
        cpa16(sm + 32768 + buf * 8192 + dst, Bl + go);
    }
}

__device__ __forceinline__ void gemm_tile(
        const __nv_bfloat16* __restrict__ Ah, const __nv_bfloat16* __restrict__ Al,
        const __nv_bfloat16* __restrict__ Bh, const __nv_bfloat16* __restrict__ Bl,
        float acc[8][4], char* sm) {
    int tid = threadIdx.x;
    int warp = tid >> 5, lane = tid & 31;
    int wm = warp >> 1, wn = warp & 1;
    int lrow = lane & 15, lseg = lane >> 4;

    load_chunk(sm, 0, Ah, Al, Bh, Bl, 0);
    cpa_commit();

    #pragma unroll 1
    for (int ch = 0; ch < 8; ch++) {
        asm volatile("cp.async.wait_group 0;\n");
        __syncthreads();
        if (ch < 7) {
            load_chunk(sm, (ch + 1) & 1, Ah, Al, Bh, Bl, (ch + 1) * 32);
            cpa_commit();
        }
        int buf = ch & 1;
        const __nv_bfloat16* pAh = (const __nv_bfloat16*)(sm + buf * 4096);
        const __nv_bfloat16* pAl = (const __nv_bfloat16*)(sm + 8192 + buf * 4096);
        const __nv_bfloat16* pBh = (const __nv_bfloat16*)(sm + 16384 + buf * 8192);
        const __nv_bfloat16* pBl = (const __nv_bfloat16*)(sm + 32768 + buf * 8192);
        #pragma unroll
        for (int ks = 0; ks < 32; ks += 16) {
            int sa = (ks >> 3) + lseg;
            unsigned ah0, ah1, ah2, ah3, al0, al1, al2, al3;
            int ar = wm * 16 + lrow;
            int aoff = swz(ar, sa);
            ldsm4(ah0, ah1, ah2, ah3, pAh + aoff);
            ldsm4(al0, al1, al2, al3, pAl + aoff);
            #pragma unroll
            for (int t = 0; t < 4; t++) {
                unsigned bh0, bh1, bh2, bh3, bl0, bl1, bl2, bl3;
                int br = wn * 64 + t * 16 + lrow;
                int boff = swz(br, sa);
                ldsm4(bh0, bh1, bh2, bh3, pBh + boff);
                ldsm4(bl0, bl1, bl2, bl3, pBl + boff);
                mma_bf16(acc[2 * t],     ah0, ah1, ah2, ah3, bh0, bh2);
                mma_bf16(acc[2 * t],     ah0, ah1, ah2, ah3, bl0, bl2);
                mma_bf16(acc[2 * t],     al0, al1, al2, al3, bh0, bh2);
                mma_bf16(acc[2 * t + 1], ah0, ah1, ah2, ah3, bh1, bh3);
                mma_bf16(acc[2 * t + 1], ah0, ah1, ah2, ah3, bl1, bl3);
                mma_bf16(acc[2 * t + 1], al0, al1, al2, al3, bh1, bh3);
            }
        }
    }
}

// ---------------- merged projection kernel: kv (0..4703) | q (4704..5095) ------
__global__ void __launch_bounds__(256, 4) proj_mma(const int* __restrict__ mode,
                                                   const float* __restrict__ bq) {
    extern __shared__ char sm[];
    int blk = blockIdx.x;
    int warp = threadIdx.x >> 5, lane = threadIdx.x & 31;
    int wm = warp >> 1, wn = warp & 1;
    int gid = lane >> 2, tg = lane & 3;

    if (blk < 4704) {   // ---- K'/V' projection ----
        int bz = blk / 196; int r = blk - bz * 196;
        int mt = r >> 2, nt = r & 3;
        int b = bz / 6, z = bz - b * 6;
        const __nv_bfloat16* Ah = g_Xh + (size_t)(bz * 3136 + mt * 64) * 256;
        const __nv_bfloat16* Al = g_Xl + (size_t)(bz * 3136 + mt * 64) * 256;
        const __nv_bfloat16* Bh = g_Wkvh + (size_t)bz * 131072 + (size_t)nt * 128 * 256;
        const __nv_bfloat16* Bl = g_Wkvl + (size_t)bz * 131072 + (size_t)nt * 128 * 256;
        float acc[8][4] = {};
        gemm_tile(Ah, Al, Bh, Bl, acc, sm);

        #pragma unroll
        for (int j = 0; j < 8; j++) {
            #pragma unroll
            for (int ee = 0; ee < 2; ee++) {
                int row = mt * 64 + wm * 16 + gid + ee * 8;
                int o0 = nt * 128 + wn * 64 + j * 8 + tg * 2;
                float v0 = acc[j][ee * 2]     + g_bKV[bz * 512 + o0];
                float v1 = acc[j][ee * 2 + 1] + g_bKV[bz * 512 + o0 + 1];
                int od = o0 & 255;
                int xy = row / 49, ef = row - xy * 49;
                int hh = od >> 5, p = od & 31;
                size_t bh = (size_t)((b * 64 + xy) * 8 + hh);
                __nv_bfloat16 h0 = __float2bfloat16_rn(v0);
                __nv_bfloat16 h1 = __float2bfloat16_rn(v1);
                __nv_bfloat16 l0 = __float2bfloat16_rn(v0 - __bfloat162float(h0));
                __nv_bfloat16 l1 = __float2bfloat16_rn(v1 - __bfloat162float(h1));
                if (o0 < 256) {
                    size_t idx = bh * 9408 + (size_t)(z * 49 + ef) * 32 + p;
                    *reinterpret_cast<__nv_bfloat162*>(g_Kh + idx) = __halves2bfloat162(h0, h1);
                    *reinterpret_cast<__nv_bfloat162*>(g_Kl + idx) = __halves2bfloat162(l0, l1);
                } else {
                    size_t idx = bh * 9728 + (size_t)p * 304 + z * 49 + ef;
                    g_Vth[idx] = h0; g_Vtl[idx] = l0;
                    g_Vth[idx + 304] = h1; g_Vtl[idx + 304] = l1;
                }
            }
        }
    } else {            // ---- Q projection ----
        int qb = blk - 4704;
        int b = qb / 98; int r = qb - b * 98;
        int mt = r >> 1, nt = r & 1;
        int tq = mode[b * 6];
        const __nv_bfloat16* Ah = g_Xh + (size_t)(b * 6 * 3136 + mt * 64) * 256;
        const __nv_bfloat16* Al = g_Xl + (size_t)(b * 6 * 3136 + mt * 64) * 256;
        const __nv_bfloat16* Bh = g_WQh + (size_t)tq * 65536 + (size_t)nt * 128 * 256;
        const __nv_bfloat16* Bl = g_WQl + (size_t)tq * 65536 + (size_t)nt * 128 * 256;
        float acc[8][4] = {};
        gemm_tile(Ah, Al, Bh, Bl, acc, sm);

        #pragma unroll
        for (int j = 0; j < 8; j++) {
            #pragma unroll
            for (int ee = 0; ee < 2; ee++) {
                int row = mt * 64 + wm * 16 + gid + ee * 8;
                int o0 = nt * 128 + wn * 64 + j * 8 + tg * 2;
                float v0 = (acc[j][ee * 2]     + bq[tq * 256 + o0])     * SCALE;
                float v1 = (acc[j][ee * 2 + 1] + bq[tq * 256 + o0 + 1]) * SCALE;
                int xy = row / 49, a = row - xy * 49;
                int hh = o0 >> 5, p = o0 & 31;
                size_t idx = (size_t)((b * 64 + xy) * 8 + hh) * 1568 + a * 32 + p;
                __nv_bfloat16 h0 = __float2bfloat16_rn(v0);
                __nv_bfloat16 h1 = __float2bfloat16_rn(v1);
                *reinterpret_cast<__nv_bfloat162*>(g_Qh + idx) = __halves2bfloat162(h0, h1);
                *reinterpret_cast<__nv_bfloat162*>(g_Ql + idx) = __halves2bfloat162(
                    __float2bfloat16_rn(v0 - __bfloat162float(h0)),
                    __float2bfloat16_rn(v1 - __bfloat162float(h1)));
            }
        }
    }
}

// ---------------- K3: tensor-core attention (R10, no reg cap) ------------------
#define SM_VTH   0
#define SM_VTL   20992
#define SM_WRED  41984
#define SM_KH    44032
#define SM_KL    64512
#define SM_QH    84992
#define SM_QL    89088
#define SM_BIAS  93184
#define SM_RED   44032
#define SM_TOTAL 111616
#define VSTR 328

__global__ void __launch_bounds__(256) attn_kernel(const float* __restrict__ pos_table) {
    extern __shared__ char sm[];
    int bh = blockIdx.x;
    int h = bh & 7, bxy = bh >> 3;
    int tid = threadIdx.x;
    int w = tid >> 5, lane = tid & 31;
    int gid = lane >> 2, tg = lane & 3;
    int lrow = lane & 15, lseg = lane >> 4;
    float* biasS = (float*)(sm + SM_BIAS);
    float* wred  = (float*)(sm + SM_WRED);

    const __nv_bfloat16* Kg_h = g_Kh + (size_t)bh * 9408;
    const __nv_bfloat16* Kg_l = g_Kl + (size_t)bh * 9408;
    const __nv_bfloat16* Vg_h = g_Vth + (size_t)bh * 9728;
    const __nv_bfloat16* Vg_l = g_Vtl + (size_t)bh * 9728;
    const __nv_bfloat16* Qg_h = g_Qh + (size_t)bh * 1568;
    const __nv_bfloat16* Qg_l = g_Ql + (size_t)bh * 1568;

    for (int i = tid; i < 240; i += 256) {
        int r = 49 + i / 16, c = i % 16;
        ((unsigned*)(sm + SM_QH))[r * 16 + c] = 0;
        ((unsigned*)(sm + SM_QL))[r * 16 + c] = 0;
    }
    {
        int r = tid >> 3, c = tid & 7;
        ((unsigned*)(sm + SM_VTH))[r * 164 + 152 + c] = 0;
        ((unsigned*)(sm + SM_VTL))[r * 164 + 152 + c] = 0;
    }
    for (int i = tid; i < 1176; i += 256) {
        int r = i >> 2, s = i & 3;
        int dst = r * 64 + ((s ^ ((r >> 1) & 3)) << 4);
        cpa16(sm + SM_KH + dst, Kg_h + r * 32 + s * 8);
        cpa16(sm + SM_KL + dst, Kg_l + r * 32 + s * 8);
    }
    for (int i = tid; i < 1216; i += 256) {
        int r = i / 38, seg = i - r * 38;
        cpa16(sm + SM_VTH + r * 656 + seg * 16, Vg_h + r * 304 + seg * 8);
        cpa16(sm + SM_VTL + r * 656 + seg * 16, Vg_l + r * 304 + seg * 8);
    }
    for (int i = tid; i < 196; i += 256) {
        int r = i >> 2, s = i & 3;
        int dst = r * 64 + ((s ^ ((r >> 1) & 3)) << 4);
        cpa16(sm + SM_QH + dst, Qg_h + r * 32 + s * 8);
        cpa16(sm + SM_QL + dst, Qg_l + r * 32 + s * 8);
    }
    cpa_commit();
    for (int i = tid; i < 2401; i += 256) {
        int a = i / 49, ef = i - a * 49;
        int au = a / 7, av = a - au * 7, eu = ef / 7, ev = ef - eu * 7;
        int idx = (au - eu + 6) * 13 + (av - ev + 6);
        biasS[i] = pos_table[idx * 8 + h];
    }
    asm volatile("cp.async.wait_group 0;\n");
    __syncthreads();

    const __nv_bfloat16* Qs_h = (const __nv_bfloat16*)(sm + SM_QH);
    const __nv_bfloat16* Qs_l = (const __nv_bfloat16*)(sm + SM_QL);
    const __nv_bfloat16* Ks_h = (const __nv_bfloat16*)(sm + SM_KH);
    const __nv_bfloat16* Ks_l = (const __nv_bfloat16*)(sm + SM_KL);
    int nb = w * 40;

    float acc[4][5][4];
    #pragma unroll
    for (int mt = 0; mt < 4; mt++)
        #pragma unroll
        for (int j = 0; j < 5; j++)
            #pragma unroll
            for (int e = 0; e < 4; e++) acc[mt][j][e] = 0.f;

    #pragma unroll
    for (int ks = 0; ks < 32; ks += 16) {
        int sa = (ks >> 3) + lseg;
        unsigned ah[4][4], al[4][4];
        #pragma unroll
        for (int mt = 0; mt < 4; mt++) {
            int ar = mt * 16 + lrow;
            int aoff = swz(ar, sa);
            ldsm4(ah[mt][0], ah[mt][1], ah[mt][2], ah[mt][3], Qs_h + aoff);
            ldsm4(al[mt][0], al[mt][1], al[mt][2], al[mt][3], Qs_l + aoff);
        }
        unsigned bhf[5][2], blf[5][2];
        #pragma unroll
        for (int jp = 0; jp < 2; jp++) {
            unsigned r0, r1, r2, r3;
            int br = nb + jp * 16 + lrow;
            int boff = swz(br, sa);
            ldsm4(r0, r1, r2, r3, Ks_h + boff);
            bhf[2 * jp][0] = r0; bhf[2 * jp][1] = r2;
            bhf[2 * jp + 1][0] = r1; bhf[2 * jp + 1][1] = r3;
            ldsm4(r0, r1, r2, r3, Ks_l + boff);
            blf[2 * jp][0] = r0; blf[2 * jp][1] = r2;
            blf[2 * jp + 1][0] = r1; blf[2 * jp + 1][1] = r3;
        }
        {
            unsigned r0, r1;
            int l = lane & 15;
            int br = nb + 32 + (l & 7);
            int sg = (ks >> 3) + (l >> 3);
            int boff = swz(br, sg);
            ldsm2(r0, r1, Ks_h + boff);
            bhf[4][0] = r0; bhf[4][1] = r1;
            ldsm2(r0, r1, Ks_l + boff);
            blf[4][0] = r0; blf[4][1] = r1;
        }
        #pragma unroll
        for (int mt = 0; mt < 4; mt++)
            #pragma unroll
            for (int j = 0; j < 5; j++) {
                mma_bf16(acc[mt][j], ah[mt][0], ah[mt][1], ah[mt][2], ah[mt][3], bhf[j][0], bhf[j][1]);
                mma_bf16(acc[mt][j], ah[mt][0], ah[mt][1], ah[mt][2], ah[mt][3], blf[j][0], blf[j][1]);
                mma_bf16(acc[mt][j], al[mt][0], al[mt][1], al[mt][2], al[mt][3], bhf[j][0], bhf[j][1]);
            }
    }

    int ef_[5][2]; bool val_[5][2];
    #pragma unroll
    for (int j = 0; j < 5; j++)
        #pragma unroll
        for (int c = 0; c < 2; c++) {
            int n = nb + j * 8 + tg * 2 + c;
            val_[j][c] = (n < NKEY);
            ef_[j][c] = n % 49;
        }
    #pragma unroll
    for (int mt = 0; mt < 4; mt++)
        #pragma unroll
        for (int half = 0; half < 2; half++) {
            int row = mt * 16 + gid + half * 8;
            #pragma unroll
            for (int j = 0; j < 5; j++)
                #pragma unroll
                for (int c = 0; c < 2; c++) {
                    float& a = acc[mt][j][half * 2 + c];
                    if (!val_[j][c]) a = -1e30f;
                    else if (row < 49) a += biasS[row * 49 + ef_[j][c]];
                }
        }

    float gmax[4][2];
    #pragma unroll
    for (int mt = 0; mt < 4; mt++)
        #pragma unroll
        for (int half = 0; half < 2; half++) {
            float m = -1e30f;
            #pragma unroll
            for (int j = 0; j < 5; j++) {
                m = fmaxf(m, acc[mt][j][half * 2]);
                m = fmaxf(m, acc[mt][j][half * 2 + 1]);
            }
            m = fmaxf(m, __shfl_xor_sync(0xffffffffu, m, 1));
            m = fmaxf(m, __shfl_xor_sync(0xffffffffu, m, 2));
            if (tg == 0) wred[(mt * 16 + gid + half * 8) * 8 + w] = m;
        }
    __syncthreads();
    #pragma unroll
    for (int mt = 0; mt < 4; mt++)
        #pragma unroll
        for (int half = 0; half < 2; half++) {
            int row = mt * 16 + gid + half * 8;
            float g = wred[row * 8];
            #pragma unroll
            for (int k = 1; k < 8; k++) g = fmaxf(g, wred[row * 8 + k]);
            gmax[mt][half] = g;
        }
    __syncthreads();
    float ginv[4][2];
    #pragma unroll
    for (int mt = 0; mt < 4; mt++)
        #pragma unroll
        for (int half = 0; half < 2; half++) {
            float s = 0.f;
            #pragma unroll
            for (int j = 0; j < 5; j++) {
                float e0 = __expf(acc[mt][j][half * 2]     - gmax[mt][half]);
                float e1 = __expf(acc[mt][j][half * 2 + 1] - gmax[mt][half]);
                acc[mt][j][half * 2] = e0; acc[mt][j][half * 2 + 1] = e1;
                s += e0 + e1;
            }
            s += __shfl_xor_sync(0xffffffffu, s, 1);
            s += __shfl_xor_sync(0xffffffffu, s, 2);
            if (tg == 0) wred[(mt * 16 + gid + half * 8) * 8 + w] = s;
        }
    __syncthreads();
    #pragma unroll
    for (int mt = 0; mt < 4; mt++)
        #pragma unroll
        for (int half = 0; half < 2; half++) {
            int row = mt * 16 + gid + half * 8;
            float s = 0.f;
            #pragma unroll
            for (int k = 0; k < 8; k++) s += wred[row * 8 + k];
            ginv[mt][half] = 1.f / s;
        }

    unsigned ph[4][5][2], pl[4][5][2];
    #pragma unroll
    for (int mt = 0; mt < 4; mt++)
        #pragma unroll
        for (int j = 0; j < 5; j++) {
            float p0 = acc[mt][j][0] * ginv[mt][0];
            float p1 = acc[mt][j][1] * ginv[mt][0];
            float p2 = acc[mt][j][2] * ginv[mt][1];
            float p3 = acc[mt][j][3] * ginv[mt][1];
            __nv_bfloat16 h0 = __float2bfloat16_rn(p0), h1 = __float2bfloat16_rn(p1);
            __nv_bfloat16 h2 = __float2bfloat16_rn(p2), h3 = __float2bfloat16_rn(p3);
            ph[mt][j][0] = pk(h0, h1); ph[mt][j][1] = pk(h2, h3);
            pl[mt][j][0] = pk(__float2bfloat16_rn(p0 - __bfloat162float(h0)),
                              __float2bfloat16_rn(p1 - __bfloat162float(h1)));
            pl[mt][j][1] = pk(__float2bfloat16_rn(p2 - __bfloat162float(h2)),
                              __float2bfloat16_rn(p3 - __bfloat162float(h3)));
        }

    const __nv_bfloat16* Vt_h = (const __nv_bfloat16*)(sm + SM_VTH);
    const __nv_bfloat16* Vt_l = (const __nv_bfloat16*)(sm + SM_VTL);
    float cc[4][4][4];
    #pragma unroll
    for (int mt = 0; mt < 4; mt++)
        #pragma unroll
        for (int nt = 0; nt < 4; nt++)
            #pragma unroll
            for (int e = 0; e < 4; e++) cc[mt][nt][e] = 0.f;

    int lcol8 = lseg << 3;
    #pragma unroll
    for (int t = 0; t < 2; t++) {
        int kb = w * 40 + t * 16;
        unsigned vh[4][2], vl[4][2];
        #pragma unroll
        for (int g = 0; g < 2; g++) {
            unsigned r0, r1, r2, r3;
            int voff = (g * 16 + lrow) * VSTR + kb + lcol8;
            ldsm4(r0, r1, r2, r3, Vt_h + voff);
            vh[2 * g][0] = r0; vh[2 * g][1] = r2;
            vh[2 * g + 1][0] = r1; vh[2 * g + 1][1] = r3;
            ldsm4(r0, r1, r2, r3, Vt_l + voff);
            vl[2 * g][0] = r0; vl[2 * g][1] = r2;
            vl[2 * g + 1][0] = r1; vl[2 * g + 1][1] = r3;
        }
        #pragma unroll
        for (int mt = 0; mt < 4; mt++) {
            unsigned a0 = ph[mt][2 * t][0], a1 = ph[mt][2 * t][1];
            unsigned a2 = ph[mt][2 * t + 1][0], a3 = ph[mt][2 * t + 1][1];
            unsigned b0 = pl[mt][2 * t][0], b1 = pl[mt][2 * t][1];
            unsigned b2 = pl[mt][2 * t + 1][0], b3 = pl[mt][2 * t + 1][1];
            #pragma unroll
            for (int nt = 0; nt < 4; nt++) {
                mma_bf16(cc[mt][nt], a0, a1, a2, a3, vh[nt][0], vh[nt][1]);
                mma_bf16(cc[mt][nt], a0, a1, a2, a3, vl[nt][0], vl[nt][1]);
                mma_bf16(cc[mt][nt], b0, b1, b2, b3, vh[nt][0], vh[nt][1]);
            }
        }
    }
    {
        int kb = w * 40 + 32;
        unsigned v8h[4], v8l[4];
        #pragma unroll
        for (int g = 0; g < 2; g++) {
            unsigned r0, r1;
            int voff = (g * 16 + lrow) * VSTR + kb;
            ldsm2(r0, r1, Vt_h + voff);
            v8h[2 * g] = r0; v8h[2 * g + 1] = r1;
            ldsm2(r0, r1, Vt_l + voff);
            v8l[2 * g] = r0; v8l[2 * g + 1] = r1;
        }
        #pragma unroll
        for (int mt = 0; mt < 4; mt++) {
            unsigned a0 = ph[mt][4][0], a1 = ph[mt][4][1];
            unsigned b0 = pl[mt][4][0], b1 = pl[mt][4][1];
            #pragma unroll
            for (int nt = 0; nt < 4; nt++) {
                mma8_bf16(cc[mt][nt], a0, a1, v8h[nt]);
                mma8_bf16(cc[mt][nt], a0, a1, v8l[nt]);
                mma8_bf16(cc[mt][nt], b0, b1, v8h[nt]);
            }
        }
    }

    float* red = (float*)(sm + SM_RED);
    __syncthreads();
    #pragma unroll
    for (int mt = 0; mt < 4; mt++)
        #pragma unroll
        for (int nt = 0; nt < 4; nt++)
            #pragma unroll
            for (int e = 0; e < 4; e++) {
                int row = mt * 16 + gid + ((e >> 1) << 3);
                int p = nt * 8 + tg * 2 + (e & 1);
                red[w * 2112 + row * 33 + p] = cc[mt][nt][e];
            }
    __syncthreads();
    for (int i = tid; i < 2048; i += 256) {
        int row = i >> 5, p = i & 31;
        if (row >= 49) continue;
        float s = 0.f;
        #pragma unroll
        for (int k = 0; k < 8; k++) s += red[k * 2112 + row * 33 + p];
        size_t base = (size_t)(bxy * 49 + row) * 256 + h * 32 + p;
        __nv_bfloat16 hv = __float2bfloat16_rn(s);
        g_AOh[base] = hv;
        g_AOl[base] = __float2bfloat16_rn(s - __bfloat162float(hv));
    }
}

// ---------------- K4: final projection -----------------------------------------
__global__ void __launch_bounds__(256, 4) ao_mma(const int* __restrict__ mode,
                                                 const float* __restrict__ ba,
                                                 float* __restrict__ out) {
    extern __shared__ char sm[];
    int blk = blockIdx.x;
    int b = blk / 98; int r = blk - b * 98;
    int mt = r >> 1, nt = r & 1;
    int ta = mode[b * 6];
    const __nv_bfloat16* Ah = g_AOh + (size_t)(b * 3136 + mt * 64) * 256;
    const __nv_bfloat16* Al = g_AOl + (size_t)(b * 3136 + mt * 64) * 256;
    const __nv_bfloat16* Bh = g_WAh + (size_t)ta * 65536 + (size_t)nt * 128 * 256;
    const __nv_bfloat16* Bl = g_WAl + (size_t)ta * 65536 + (size_t)nt * 128 * 256;
    float acc[8][4] = {};
    gemm_tile(Ah, Al, Bh, Bl, acc, sm);

    int warp = threadIdx.x >> 5, lane = threadIdx.x & 31;
    int wm = warp >> 1, wn = warp & 1;
    int gid = lane >> 2, tg = lane & 3;
    #pragma unroll
    for (int j = 0; j < 8; j++) {
        #pragma unroll
        for (int ee = 0; ee < 2; ee++) {
            int row = mt * 64 + wm * 16 + gid + ee * 8;
            int o0 = nt * 128 + wn * 64 + j * 8 + tg * 2;
            float2 v;
            v.x = acc[j][ee * 2]     + ba[ta * 256 + o0];
            v.y = acc[j][ee * 2 + 1] + ba[ta * 256 + o0 + 1];
            *reinterpret_cast<float2*>(out + (size_t)(b * 3136 + row) * 256 + o0) = v;
        }
    }
}

// ---------------- launch --------------------------------------------------------
extern "C" void kernel_launch(void* const* d_in, const int* in_sizes, int n_in,
                              void* d_out, int out_size) {
    const float* x    = (const float*)d_in[0];
    const int*   mode = (const int*)  d_in[1];
    const float* Wq   = (const float*)d_in[2];
    const float* bq   = (const float*)d_in[3];
    const float* Wk   = (const float*)d_in[4];
    const float* bk   = (const float*)d_in[5];
    const float* Wv   = (const float*)d_in[6];
    const float* bv   = (const float*)d_in[7];
    const float* Wa   = (const float*)d_in[8];
    const float* ba   = (const float*)d_in[9];
    const float* ratt = (const float*)d_in[10];
    const float* rmsg = (const float*)d_in[11];
    const float* post = (const float*)d_in[12];
    float* out = (float*)d_out;

    cudaFuncSetAttribute(attn_kernel, cudaFuncAttributeMaxDynamicSharedMemorySize, SM_TOTAL);
    cudaFuncSetAttribute(proj_mma, cudaFuncAttributeMaxDynamicSharedMemorySize, 49152);
    cudaFuncSetAttribute(ao_mma,   cudaFuncAttributeMaxDynamicSharedMemorySize, 49152);

    pack_x    <<<18816, 256>>>(reinterpret_cast<const float4*>(x));
    pack_qa   <<<128, 256>>>(Wq, Wa);
    combine_w <<<192, 256>>>(Wk, bk, Wv, bv, ratt, rmsg, mode);
    proj_mma  <<<5096, 256, 49152>>>(mode, bq);
    attn_kernel<<<2048, 256, SM_TOTAL>>>(post);
    ao_mma    <<<392, 256, 49152>>>(mode, ba, out);
}

// round 16
// speedup vs baseline: 1.1531x; 1.0323x over previous
#include <cuda_runtime.h>
#include <cuda_bf16.h>
#include <math.h>

// ---------------------------------------------------------------------------
// HeteroAttention R14: R13 + attention restructured into two row-passes
// (live regs ~110) with bias-via-LDG and 3-stage smem tree reduce, enabling
// __launch_bounds__(256,2) -> 2 CTAs/SM on attn. proj/packs/ao unchanged.
// ---------------------------------------------------------------------------

#define NKEY  294
#define SCALE 0.17677669529663687f

// ---------------- scratch ----------------------------------------------------
__device__ __nv_bfloat16 g_Xh[19267584];     // [bz*3136+t][256]
__device__ __nv_bfloat16 g_Xl[19267584];
__device__ __nv_bfloat16 g_Wkvh[24*512*256]; // [bz][o(512)][d]
__device__ __nv_bfloat16 g_Wkvl[24*512*256];
__device__ float         g_bKV [24*512];
__device__ __nv_bfloat16 g_WQh[2*65536];
__device__ __nv_bfloat16 g_WQl[2*65536];
__device__ __nv_bfloat16 g_WAh[2*65536];
__device__ __nv_bfloat16 g_WAl[2*65536];
__device__ __nv_bfloat16 g_Kh[2048*9408];    // [bh][n(294)][p(32)]
__device__ __nv_bfloat16 g_Kl[2048*9408];
__device__ __nv_bfloat16 g_Vth[2048*9728];   // [bh][p(32)][n(304)] pad cols zero
__device__ __nv_bfloat16 g_Vtl[2048*9728];
__device__ __nv_bfloat16 g_Qh[2048*1568];    // [bh][a(49)][p(32)]
__device__ __nv_bfloat16 g_Ql[2048*1568];
__device__ __nv_bfloat16 g_AOh[256*12544];   // [bxy*49+a][256]
__device__ __nv_bfloat16 g_AOl[256*12544];

// ---------------- helpers -----------------------------------------------------
__device__ __forceinline__ unsigned pk(__nv_bfloat16 a, __nv_bfloat16 b) {
    __nv_bfloat162 t = __halves2bfloat162(a, b);
    return *reinterpret_cast<unsigned*>(&t);
}
__device__ __forceinline__ void split4(float4 f, uint2& h, uint2& l) {
    __nv_bfloat16 h0 = __float2bfloat16_rn(f.x), h1 = __float2bfloat16_rn(f.y);
    __nv_bfloat16 h2 = __float2bfloat16_rn(f.z), h3 = __float2bfloat16_rn(f.w);
    __nv_bfloat16 l0 = __float2bfloat16_rn(f.x - __bfloat162float(h0));
    __nv_bfloat16 l1 = __float2bfloat16_rn(f.y - __bfloat162float(h1));
    __nv_bfloat16 l2 = __float2bfloat16_rn(f.z - __bfloat162float(h2));
    __nv_bfloat16 l3 = __float2bfloat16_rn(f.w - __bfloat162float(h3));
    h.x = pk(h0, h1); h.y = pk(h2, h3);
    l.x = pk(l0, l1); l.y = pk(l2, l3);
}
__device__ __forceinline__ void mma_bf16(float* c, unsigned a0, unsigned a1,
                                         unsigned a2, unsigned a3,
                                         unsigned b0, unsigned b1) {
    asm volatile(
        "mma.sync.aligned.m16n8k16.row.col.f32.bf16.bf16.f32 "
        "{%0,%1,%2,%3}, {%4,%5,%6,%7}, {%8,%9}, {%0,%1,%2,%3};\n"
        : "+f"(c[0]), "+f"(c[1]), "+f"(c[2]), "+f"(c[3])
        : "r"(a0), "r"(a1), "r"(a2), "r"(a3), "r"(b0), "r"(b1));
}
__device__ __forceinline__ void mma8_bf16(float* c, unsigned a0, unsigned a1,
                                          unsigned b0) {
    asm volatile(
        "mma.sync.aligned.m16n8k8.row.col.f32.bf16.bf16.f32 "
        "{%0,%1,%2,%3}, {%4,%5}, {%6}, {%0,%1,%2,%3};\n"
        : "+f"(c[0]), "+f"(c[1]), "+f"(c[2]), "+f"(c[3])
        : "r"(a0), "r"(a1), "r"(b0));
}
__device__ __forceinline__ void ldsm4(unsigned& r0, unsigned& r1,
                                      unsigned& r2, unsigned& r3, const void* p) {
    unsigned a = (unsigned)__cvta_generic_to_shared(p);
    asm volatile("ldmatrix.sync.aligned.m8n8.x4.shared.b16 {%0,%1,%2,%3}, [%4];\n"
                 : "=r"(r0), "=r"(r1), "=r"(r2), "=r"(r3) : "r"(a));
}
__device__ __forceinline__ void ldsm2(unsigned& r0, unsigned& r1, const void* p) {
    unsigned a = (unsigned)__cvta_generic_to_shared(p);
    asm volatile("ldmatrix.sync.aligned.m8n8.x2.shared.b16 {%0,%1}, [%2];\n"
                 : "=r"(r0), "=r"(r1) : "r"(a));
}
__device__ __forceinline__ void cpa16(void* dst, const void* src) {
    unsigned d = (unsigned)__cvta_generic_to_shared(dst);
    asm volatile("cp.async.cg.shared.global [%0], [%1], 16;\n" :: "r"(d), "l"(src));
}
__device__ __forceinline__ void cpa_commit() { asm volatile("cp.async.commit_group;\n"); }
__device__ __forceinline__ int swz(int row, int seg) {
    return row * 32 + ((seg ^ ((row >> 1) & 3)) << 3);
}

// ---------------- pack kernels ------------------------------------------------
__global__ void pack_x(const float4* __restrict__ x) {
    int i = blockIdx.x * 256 + threadIdx.x;
    float4 f = x[i];
    uint2 h, l; split4(f, h, l);
    reinterpret_cast<uint2*>(g_Xh)[i] = h;
    reinterpret_cast<uint2*>(g_Xl)[i] = l;
}
__global__ void pack_qa(const float* __restrict__ Wq, const float* __restrict__ Wa) {
    int i = blockIdx.x * 256 + threadIdx.x;
    uint2 h, l;
    float4 fq = reinterpret_cast<const float4*>(Wq)[i];
    split4(fq, h, l);
    reinterpret_cast<uint2*>(g_WQh)[i] = h;
    reinterpret_cast<uint2*>(g_WQl)[i] = l;
    float4 fa = reinterpret_cast<const float4*>(Wa)[i];
    split4(fa, h, l);
    reinterpret_cast<uint2*>(g_WAh)[i] = h;
    reinterpret_cast<uint2*>(g_WAl)[i] = l;
}

// ---------------- K0b: fold relation matrices --------------------------------
__global__ void combine_w(const float* __restrict__ Wk, const float* __restrict__ bk,
                          const float* __restrict__ Wv, const float* __restrict__ bv,
                          const float* __restrict__ ratt, const float* __restrict__ rmsg,
                          const int* __restrict__ mode) {
    __shared__ float att_s[32 * 33];
    __shared__ float msg_s[32 * 33];
    __shared__ float w_s[32 * 256];
    int bz = blockIdx.x >> 3, h = blockIdx.x & 7;
    int b = bz / 6, z = bz - b * 6;
    int t   = mode[b * 6 + z];
    int rel = mode[b * 6] * 2 + t;
    int tid = threadIdx.x;

    for (int i = tid; i < 1024; i += 256) {
        int p = i >> 5, q = i & 31;
        att_s[p * 33 + q] = ratt[((rel * 8 + h) * 32 + p) * 32 + q];
        msg_s[p * 33 + q] = rmsg[((rel * 8 + h) * 32 + p) * 32 + q];
    }
    const float* WkB = Wk + (t * 256 + h * 32) * 256;
    for (int i = tid; i < 8192; i += 256) w_s[i] = WkB[i];
    __syncthreads();
    {
        int p = tid & 31;
        for (int d = tid >> 5; d < 256; d += 8) {
            float acc = 0.f;
            #pragma unroll
            for (int q = 0; q < 32; q++) acc = fmaf(att_s[p * 33 + q], w_s[q * 256 + d], acc);
            size_t idx = (size_t)bz * 131072 + (size_t)(h * 32 + p) * 256 + d;
            __nv_bfloat16 hv = __float2bfloat16_rn(acc);
            g_Wkvh[idx] = hv;
            g_Wkvl[idx] = __float2bfloat16_rn(acc - __bfloat162float(hv));
        }
        if (tid < 32) {
            float acc = 0.f;
            #pragma unroll
            for (int q = 0; q < 32; q++) acc = fmaf(att_s[tid * 33 + q], bk[t * 256 + h * 32 + q], acc);
            g_bKV[bz * 512 + h * 32 + tid] = acc;
        }
    }
    __syncthreads();
    const float* WvB = Wv + (t * 256 + h * 32) * 256;
    for (int i = tid; i < 8192; i += 256) w_s[i] = WvB[i];
    __syncthreads();
    {
        int qo = tid & 31;
        for (int d = tid >> 5; d < 256; d += 8) {
            float acc = 0.f;
            #pragma unroll
            for (int p = 0; p < 32; p++) acc = fmaf(msg_s[p * 33 + qo], w_s[p * 256 + d], acc);
            size_t idx = (size_t)bz * 131072 + (size_t)(256 + h * 32 + qo) * 256 + d;
            __nv_bfloat16 hv = __float2bfloat16_rn(acc);
            g_Wkvh[idx] = hv;
            g_Wkvl[idx] = __float2bfloat16_rn(acc - __bfloat162float(hv));
        }
        if (tid < 32) {
            float acc = 0.f;
            #pragma unroll
            for (int p = 0; p < 32; p++) acc = fmaf(msg_s[p * 33 + tid], bv[t * 256 + h * 32 + p], acc);
            g_bKV[bz * 512 + 256 + h * 32 + tid] = acc;
        }
    }
}

// ---------------- 64x128x256 tensor-core tile (swizzled smem) ------------------
__device__ __forceinline__ void load_chunk(char* sm, int buf,
        const __nv_bfloat16* __restrict__ Ah, const __nv_bfloat16* __restrict__ Al,
        const __nv_bfloat16* __restrict__ Bh, const __nv_bfloat16* __restrict__ Bl,
        int kc) {
    int tid = threadIdx.x;
    {   // A: 64 rows x 4 segs
        int r = tid >> 2, s = tid & 3;
        int dst = r * 64 + ((s ^ ((r >> 1) & 3)) << 4);
        int go = r * 256 + kc + s * 8;
        cpa16(sm + buf * 4096 + dst, Ah + go);
        cpa16(sm + 8192 + buf * 4096 + dst, Al + go);
    }
    #pragma unroll
    for (int i = 0; i < 2; i++) {   // B: 128 rows x 4 segs
        int id = tid + i * 256;
        int r = id >> 2, s = id & 3;
        int dst = r * 64 + ((s ^ ((r >> 1) & 3)) << 4);
        int go = r * 256 + kc + s * 8;
        cpa16(sm + 16384 + buf * 8192 + dst, Bh + go);
        cpa16(sm + 32768 + buf * 8192 + dst, Bl + go);
    }
}

__device__ __forceinline__ void gemm_tile(
        const __nv_bfloat16* __restrict__ Ah, const __nv_bfloat16* __restrict__ Al,
        const __nv_bfloat16* __restrict__ Bh, const __nv_bfloat16* __restrict__ Bl,
        float acc[8][4], char* sm) {
    int tid = threadIdx.x;
    int warp = tid >> 5, lane = tid & 31;
    int wm = warp >> 1, wn = warp & 1;
    int lrow = lane & 15, lseg = lane >> 4;

    load_chunk(sm, 0, Ah, Al, Bh, Bl, 0);
    cpa_commit();

    #pragma unroll 1
    for (int ch = 0; ch < 8; ch++) {
        asm volatile("cp.async.wait_group 0;\n");
        __syncthreads();
        if (ch < 7) {
            load_chunk(sm, (ch + 1) & 1, Ah, Al, Bh, Bl, (ch + 1) * 32);
            cpa_commit();
        }
        int buf = ch & 1;
        const __nv_bfloat16* pAh = (const __nv_bfloat16*)(sm + buf * 4096);
        const __nv_bfloat16* pAl = (const __nv_bfloat16*)(sm + 8192 + buf * 4096);
        const __nv_bfloat16* pBh = (const __nv_bfloat16*)(sm + 16384 + buf * 8192);
        const __nv_bfloat16* pBl = (const __nv_bfloat16*)(sm + 32768 + buf * 8192);
        #pragma unroll
        for (int ks = 0; ks < 32; ks += 16) {
            int sa = (ks >> 3) + lseg;
            unsigned ah0, ah1, ah2, ah3, al0, al1, al2, al3;
            int ar = wm * 16 + lrow;
            int aoff = swz(ar, sa);
            ldsm4(ah0, ah1, ah2, ah3, pAh + aoff);
            ldsm4(al0, al1, al2, al3, pAl + aoff);
            #pragma unroll
            for (int t = 0; t < 4; t++) {
                unsigned bh0, bh1, bh2, bh3, bl0, bl1, bl2, bl3;
                int br = wn * 64 + t * 16 + lrow;
                int boff = swz(br, sa);
                ldsm4(bh0, bh1, bh2, bh3, pBh + boff);
                ldsm4(bl0, bl1, bl2, bl3, pBl + boff);
                mma_bf16(acc[2 * t],     ah0, ah1, ah2, ah3, bh0, bh2);
                mma_bf16(acc[2 * t],     ah0, ah1, ah2, ah3, bl0, bl2);
                mma_bf16(acc[2 * t],     al0, al1, al2, al3, bh0, bh2);
                mma_bf16(acc[2 * t + 1], ah0, ah1, ah2, ah3, bh1, bh3);
                mma_bf16(acc[2 * t + 1], ah0, ah1, ah2, ah3, bl1, bl3);
                mma_bf16(acc[2 * t + 1], al0, al1, al2, al3, bh1, bh3);
            }
        }
    }
}

// ---------------- merged projection kernel: kv (0..4703) | q (4704..5095) ------
__global__ void __launch_bounds__(256, 4) proj_mma(const int* __restrict__ mode,
                                                   const float* __restrict__ bq) {
    extern __shared__ char sm[];
    int blk = blockIdx.x;
    int warp = threadIdx.x >> 5, lane = threadIdx.x & 31;
    int wm = warp >> 1, wn = warp & 1;
    int gid = lane >> 2, tg = lane & 3;

    if (blk < 4704) {   // ---- K'/V' projection ----
        int bz = blk / 196; int r = blk - bz * 196;
        int mt = r >> 2, nt = r & 3;
        int b = bz / 6, z = bz - b * 6;
        const __nv_bfloat16* Ah = g_Xh + (size_t)(bz * 3136 + mt * 64) * 256;
        const __nv_bfloat16* Al = g_Xl + (size_t)(bz * 3136 + mt * 64) * 256;
        const __nv_bfloat16* Bh = g_Wkvh + (size_t)bz * 131072 + (size_t)nt * 128 * 256;
        const __nv_bfloat16* Bl = g_Wkvl + (size_t)bz * 131072 + (size_t)nt * 128 * 256;
        float acc[8][4] = {};
        gemm_tile(Ah, Al, Bh, Bl, acc, sm);

        #pragma unroll
        for (int j = 0; j < 8; j++) {
            #pragma unroll
            for (int ee = 0; ee < 2; ee++) {
                int row = mt * 64 + wm * 16 + gid + ee * 8;
                int o0 = nt * 128 + wn * 64 + j * 8 + tg * 2;
                float v0 = acc[j][ee * 2]     + g_bKV[bz * 512 + o0];
                float v1 = acc[j][ee * 2 + 1] + g_bKV[bz * 512 + o0 + 1];
                int od = o0 & 255;
                int xy = row / 49, ef = row - xy * 49;
                int hh = od >> 5, p = od & 31;
                size_t bh = (size_t)((b * 64 + xy) * 8 + hh);
                __nv_bfloat16 h0 = __float2bfloat16_rn(v0);
                __nv_bfloat16 h1 = __float2bfloat16_rn(v1);
                __nv_bfloat16 l0 = __float2bfloat16_rn(v0 - __bfloat162float(h0));
                __nv_bfloat16 l1 = __float2bfloat16_rn(v1 - __bfloat162float(h1));
                if (o0 < 256) {
                    size_t idx = bh * 9408 + (size_t)(z * 49 + ef) * 32 + p;
                    *reinterpret_cast<__nv_bfloat162*>(g_Kh + idx) = __halves2bfloat162(h0, h1);
                    *reinterpret_cast<__nv_bfloat162*>(g_Kl + idx) = __halves2bfloat162(l0, l1);
                } else {
                    size_t idx = bh * 9728 + (size_t)p * 304 + z * 49 + ef;
                    g_Vth[idx] = h0; g_Vtl[idx] = l0;
                    g_Vth[idx + 304] = h1; g_Vtl[idx + 304] = l1;
                }
            }
        }
    } else {            // ---- Q projection ----
        int qb = blk - 4704;
        int b = qb / 98; int r = qb - b * 98;
        int mt = r >> 1, nt = r & 1;
        int tq = mode[b * 6];
        const __nv_bfloat16* Ah = g_Xh + (size_t)(b * 6 * 3136 + mt * 64) * 256;
        const __nv_bfloat16* Al = g_Xl + (size_t)(b * 6 * 3136 + mt * 64) * 256;
        const __nv_bfloat16* Bh = g_WQh + (size_t)tq * 65536 + (size_t)nt * 128 * 256;
        const __nv_bfloat16* Bl = g_WQl + (size_t)tq * 65536 + (size_t)nt * 128 * 256;
        float acc[8][4] = {};
        gemm_tile(Ah, Al, Bh, Bl, acc, sm);

        #pragma unroll
        for (int j = 0; j < 8; j++) {
            #pragma unroll
            for (int ee = 0; ee < 2; ee++) {
                int row = mt * 64 + wm * 16 + gid + ee * 8;
                int o0 = nt * 128 + wn * 64 + j * 8 + tg * 2;
                float v0 = (acc[j][ee * 2]     + bq[tq * 256 + o0])     * SCALE;
                float v1 = (acc[j][ee * 2 + 1] + bq[tq * 256 + o0 + 1]) * SCALE;
                int xy = row / 49, a = row - xy * 49;
                int hh = o0 >> 5, p = o0 & 31;
                size_t idx = (size_t)((b * 64 + xy) * 8 + hh) * 1568 + a * 32 + p;
                __nv_bfloat16 h0 = __float2bfloat16_rn(v0);
                __nv_bfloat16 h1 = __float2bfloat16_rn(v1);
                *reinterpret_cast<__nv_bfloat162*>(g_Qh + idx) = __halves2bfloat162(h0, h1);
                *reinterpret_cast<__nv_bfloat162*>(g_Ql + idx) = __halves2bfloat162(
                    __float2bfloat16_rn(v0 - __bfloat162float(h0)),
                    __float2bfloat16_rn(v1 - __bfloat162float(h1)));
            }
        }
    }
}

// ---------------- K3: tensor-core attention (two row-passes, 2 CTAs/SM) --------
#define SM_VTH   0         // 32 x 328 halves = 20992
#define SM_VTL   20992
#define SM_WRED  41984     // 64*8 floats = 2048
#define SM_KH    44032     // 320 x 32 halves = 20480
#define SM_KL    64512
#define SM_QH    84992     // 64 x 32 halves = 4096
#define SM_QL    89088
#define SM_RED1  93184     // 4 x 32 x 33 floats = 16896
#define SM_TOTAL 110080
#define VSTR 328

__global__ void __launch_bounds__(256, 2) attn_kernel(const float* __restrict__ pos_table) {
    extern __shared__ char sm[];
    int bh = blockIdx.x;
    int h = bh & 7, bxy = bh >> 3;
    int tid = threadIdx.x;
    int w = tid >> 5, lane = tid & 31;
    int gid = lane >> 2, tg = lane & 3;
    int lrow = lane & 15, lseg = lane >> 4;
    float* wred = (float*)(sm + SM_WRED);
    float* red1 = (float*)(sm + SM_RED1);

    const __nv_bfloat16* Kg_h = g_Kh + (size_t)bh * 9408;
    const __nv_bfloat16* Kg_l = g_Kl + (size_t)bh * 9408;
    const __nv_bfloat16* Vg_h = g_Vth + (size_t)bh * 9728;
    const __nv_bfloat16* Vg_l = g_Vtl + (size_t)bh * 9728;
    const __nv_bfloat16* Qg_h = g_Qh + (size_t)bh * 1568;
    const __nv_bfloat16* Qg_l = g_Ql + (size_t)bh * 1568;

    // zero Q pad rows 49..63 and Vt pad cols 304..319
    for (int i = tid; i < 240; i += 256) {
        int r = 49 + i / 16, c = i % 16;
        ((unsigned*)(sm + SM_QH))[r * 16 + c] = 0;
        ((unsigned*)(sm + SM_QL))[r * 16 + c] = 0;
    }
    {
        int r = tid >> 3, c = tid & 7;
        ((unsigned*)(sm + SM_VTH))[r * 164 + 152 + c] = 0;
        ((unsigned*)(sm + SM_VTL))[r * 164 + 152 + c] = 0;
    }
    for (int i = tid; i < 1176; i += 256) {            // K: 294 rows x 4 segs
        int r = i >> 2, s = i & 3;
        int dst = r * 64 + ((s ^ ((r >> 1) & 3)) << 4);
        cpa16(sm + SM_KH + dst, Kg_h + r * 32 + s * 8);
        cpa16(sm + SM_KL + dst, Kg_l + r * 32 + s * 8);
    }
    for (int i = tid; i < 1216; i += 256) {            // Vt: 32 rows x 38 segs
        int r = i / 38, seg = i - r * 38;
        cpa16(sm + SM_VTH + r * 656 + seg * 16, Vg_h + r * 304 + seg * 8);
        cpa16(sm + SM_VTL + r * 656 + seg * 16, Vg_l + r * 304 + seg * 8);
    }
    for (int i = tid; i < 196; i += 256) {             // Q: 49 rows x 4 segs
        int r = i >> 2, s = i & 3;
        int dst = r * 64 + ((s ^ ((r >> 1) & 3)) << 4);
        cpa16(sm + SM_QH + dst, Qg_h + r * 32 + s * 8);
        cpa16(sm + SM_QL + dst, Qg_l + r * 32 + s * 8);
    }
    cpa_commit();

    const __nv_bfloat16* Qs_h = (const __nv_bfloat16*)(sm + SM_QH);
    const __nv_bfloat16* Qs_l = (const __nv_bfloat16*)(sm + SM_QL);
    const __nv_bfloat16* Ks_h = (const __nv_bfloat16*)(sm + SM_KH);
    const __nv_bfloat16* Ks_l = (const __nv_bfloat16*)(sm + SM_KL);
    const __nv_bfloat16* Vt_h = (const __nv_bfloat16*)(sm + SM_VTH);
    const __nv_bfloat16* Vt_l = (const __nv_bfloat16*)(sm + SM_VTL);
    int nb = w * 40;

    // per-(j,c) key metadata (independent of row pass)
    int bidx[5][2]; bool val_[5][2];
    #pragma unroll
    for (int j = 0; j < 5; j++)
        #pragma unroll
        for (int c = 0; c < 2; c++) {
            int n = nb + j * 8 + tg * 2 + c;
            val_[j][c] = (n < NKEY);
            int ef = n % 49;
            int eu = ef / 7, ev = ef - eu * 7;
            bidx[j][c] = (6 - eu) * 13 + (6 - ev);
        }

    asm volatile("cp.async.wait_group 0;\n");
    __syncthreads();

    #pragma unroll 1
    for (int mtp = 0; mtp < 2; mtp++) {
        int mb = mtp * 32;

        // ---- QK^T for rows [mb, mb+32) ----
        float acc[2][5][4];
        #pragma unroll
        for (int mtl = 0; mtl < 2; mtl++)
            #pragma unroll
            for (int j = 0; j < 5; j++)
                #pragma unroll
                for (int e = 0; e < 4; e++) acc[mtl][j][e] = 0.f;

        #pragma unroll
        for (int ks = 0; ks < 32; ks += 16) {
            int sa = (ks >> 3) + lseg;
            unsigned ah[2][4], al[2][4];
            #pragma unroll
            for (int mtl = 0; mtl < 2; mtl++) {
                int aoff = swz(mb + mtl * 16 + lrow, sa);
                ldsm4(ah[mtl][0], ah[mtl][1], ah[mtl][2], ah[mtl][3], Qs_h + aoff);
                ldsm4(al[mtl][0], al[mtl][1], al[mtl][2], al[mtl][3], Qs_l + aoff);
            }
            unsigned bhf[5][2], blf[5][2];
            #pragma unroll
            for (int jp = 0; jp < 2; jp++) {
                unsigned r0, r1, r2, r3;
                int boff = swz(nb + jp * 16 + lrow, sa);
                ldsm4(r0, r1, r2, r3, Ks_h + boff);
                bhf[2 * jp][0] = r0; bhf[2 * jp][1] = r2;
                bhf[2 * jp + 1][0] = r1; bhf[2 * jp + 1][1] = r3;
                ldsm4(r0, r1, r2, r3, Ks_l + boff);
                blf[2 * jp][0] = r0; blf[2 * jp][1] = r2;
                blf[2 * jp + 1][0] = r1; blf[2 * jp + 1][1] = r3;
            }
            {
                unsigned r0, r1;
                int l = lane & 15;
                int boff = swz(nb + 32 + (l & 7), (ks >> 3) + (l >> 3));
                ldsm2(r0, r1, Ks_h + boff);
                bhf[4][0] = r0; bhf[4][1] = r1;
                ldsm2(r0, r1, Ks_l + boff);
                blf[4][0] = r0; blf[4][1] = r1;
            }
            #pragma unroll
            for (int mtl = 0; mtl < 2; mtl++)
                #pragma unroll
                for (int j = 0; j < 5; j++) {
                    mma_bf16(acc[mtl][j], ah[mtl][0], ah[mtl][1], ah[mtl][2], ah[mtl][3], bhf[j][0], bhf[j][1]);
                    mma_bf16(acc[mtl][j], ah[mtl][0], ah[mtl][1], ah[mtl][2], ah[mtl][3], blf[j][0], blf[j][1]);
                    mma_bf16(acc[mtl][j], al[mtl][0], al[mtl][1], al[mtl][2], al[mtl][3], bhf[j][0], bhf[j][1]);
                }
        }

        // ---- bias (via pos_table LDG) + mask ----
        #pragma unroll
        for (int mtl = 0; mtl < 2; mtl++)
            #pragma unroll
            for (int half = 0; half < 2; half++) {
                int row = mb + mtl * 16 + gid + half * 8;
                bool vr = (row < 49);
                int au = row / 7, av = row - au * 7;
                int ridx = au * 13 + av;
                #pragma unroll
                for (int j = 0; j < 5; j++)
                    #pragma unroll
                    for (int c = 0; c < 2; c++) {
                        float& a = acc[mtl][j][half * 2 + c];
                        if (!val_[j][c]) a = -1e30f;
                        else if (vr) a += __ldg(pos_table + (ridx + bidx[j][c]) * 8 + h);
                    }
            }

        // ---- softmax ----
        float gmax[2][2];
        #pragma unroll
        for (int mtl = 0; mtl < 2; mtl++)
            #pragma unroll
            for (int half = 0; half < 2; half++) {
                float m = -1e30f;
                #pragma unroll
                for (int j = 0; j < 5; j++) {
                    m = fmaxf(m, acc[mtl][j][half * 2]);
                    m = fmaxf(m, acc[mtl][j][half * 2 + 1]);
                }
                m = fmaxf(m, __shfl_xor_sync(0xffffffffu, m, 1));
                m = fmaxf(m, __shfl_xor_sync(0xffffffffu, m, 2));
                if (tg == 0) wred[(mb + mtl * 16 + gid + half * 8) * 8 + w] = m;
            }
        __syncthreads();
        #pragma unroll
        for (int mtl = 0; mtl < 2; mtl++)
            #pragma unroll
            for (int half = 0; half < 2; half++) {
                int row = mb + mtl * 16 + gid + half * 8;
                float g = wred[row * 8];
                #pragma unroll
                for (int k = 1; k < 8; k++) g = fmaxf(g, wred[row * 8 + k]);
                gmax[mtl][half] = g;
            }
        __syncthreads();
        float ginv[2][2];
        #pragma unroll
        for (int mtl = 0; mtl < 2; mtl++)
            #pragma unroll
            for (int half = 0; half < 2; half++) {
                float s = 0.f;
                #pragma unroll
                for (int j = 0; j < 5; j++) {
                    float e0 = __expf(acc[mtl][j][half * 2]     - gmax[mtl][half]);
                    float e1 = __expf(acc[mtl][j][half * 2 + 1] - gmax[mtl][half]);
                    acc[mtl][j][half * 2] = e0; acc[mtl][j][half * 2 + 1] = e1;
                    s += e0 + e1;
                }
                s += __shfl_xor_sync(0xffffffffu, s, 1);
                s += __shfl_xor_sync(0xffffffffu, s, 2);
                if (tg == 0) wred[(mb + mtl * 16 + gid + half * 8) * 8 + w] = s;
            }
        __syncthreads();
        #pragma unroll
        for (int mtl = 0; mtl < 2; mtl++)
            #pragma unroll
            for (int half = 0; half < 2; half++) {
                int row = mb + mtl * 16 + gid + half * 8;
                float s = 0.f;
                #pragma unroll
                for (int k = 0; k < 8; k++) s += wred[row * 8 + k];
                ginv[mtl][half] = 1.f / s;
            }

        // ---- pack P to bf16 hi/lo ----
        unsigned ph[2][5][2], pl[2][5][2];
        #pragma unroll
        for (int mtl = 0; mtl < 2; mtl++)
            #pragma unroll
            for (int j = 0; j < 5; j++) {
                float p0 = acc[mtl][j][0] * ginv[mtl][0];
                float p1 = acc[mtl][j][1] * ginv[mtl][0];
                float p2 = acc[mtl][j][2] * ginv[mtl][1];
                float p3 = acc[mtl][j][3] * ginv[mtl][1];
                __nv_bfloat16 h0 = __float2bfloat16_rn(p0), h1 = __float2bfloat16_rn(p1);
                __nv_bfloat16 h2 = __float2bfloat16_rn(p2), h3 = __float2bfloat16_rn(p3);
                ph[mtl][j][0] = pk(h0, h1); ph[mtl][j][1] = pk(h2, h3);
                pl[mtl][j][0] = pk(__float2bfloat16_rn(p0 - __bfloat162float(h0)),
                                   __float2bfloat16_rn(p1 - __bfloat162float(h1)));
                pl[mtl][j][1] = pk(__float2bfloat16_rn(p2 - __bfloat162float(h2)),
                                   __float2bfloat16_rn(p3 - __bfloat162float(h3)));
            }

        // ---- P·V ----
        float cc[2][4][4];
        #pragma unroll
        for (int mtl = 0; mtl < 2; mtl++)
            #pragma unroll
            for (int nt = 0; nt < 4; nt++)
                #pragma unroll
                for (int e = 0; e < 4; e++) cc[mtl][nt][e] = 0.f;

        int lcol8 = lseg << 3;
        #pragma unroll
        for (int t = 0; t < 2; t++) {
            int kb = w * 40 + t * 16;
            unsigned vh[4][2], vl[4][2];
            #pragma unroll
            for (int g = 0; g < 2; g++) {
                unsigned r0, r1, r2, r3;
                int voff = (g * 16 + lrow) * VSTR + kb + lcol8;
                ldsm4(r0, r1, r2, r3, Vt_h + voff);
                vh[2 * g][0] = r0; vh[2 * g][1] = r2;
                vh[2 * g + 1][0] = r1; vh[2 * g + 1][1] = r3;
                ldsm4(r0, r1, r2, r3, Vt_l + voff);
                vl[2 * g][0] = r0; vl[2 * g][1] = r2;
                vl[2 * g + 1][0] = r1; vl[2 * g + 1][1] = r3;
            }
            #pragma unroll
            for (int mtl = 0; mtl < 2; mtl++) {
                unsigned a0 = ph[mtl][2 * t][0], a1 = ph[mtl][2 * t][1];
                unsigned a2 = ph[mtl][2 * t + 1][0], a3 = ph[mtl][2 * t + 1][1];
                unsigned b0 = pl[mtl][2 * t][0], b1 = pl[mtl][2 * t][1];
                unsigned b2 = pl[mtl][2 * t + 1][0], b3 = pl[mtl][2 * t + 1][1];
                #pragma unroll
                for (int nt = 0; nt < 4; nt++) {
                    mma_bf16(cc[mtl][nt], a0, a1, a2, a3, vh[nt][0], vh[nt][1]);
                    mma_bf16(cc[mtl][nt], a0, a1, a2, a3, vl[nt][0], vl[nt][1]);
                    mma_bf16(cc[mtl][nt], b0, b1, b2, b3, vh[nt][0], vh[nt][1]);
                }
            }
        }
        {   // k8 remainder
            int kb = w * 40 + 32;
            unsigned v8h[4], v8l[4];
            #pragma unroll
            for (int g = 0; g < 2; g++) {
                unsigned r0, r1;
                int voff = (g * 16 + lrow) * VSTR + kb;
                ldsm2(r0, r1, Vt_h + voff);
                v8h[2 * g] = r0; v8h[2 * g + 1] = r1;
                ldsm2(r0, r1, Vt_l + voff);
                v8l[2 * g] = r0; v8l[2 * g + 1] = r1;
            }
            #pragma unroll
            for (int mtl = 0; mtl < 2; mtl++) {
                unsigned a0 = ph[mtl][4][0], a1 = ph[mtl][4][1];
                unsigned b0 = pl[mtl][4][0], b1 = pl[mtl][4][1];
                #pragma unroll
                for (int nt = 0; nt < 4; nt++) {
                    mma8_bf16(cc[mtl][nt], a0, a1, v8h[nt]);
                    mma8_bf16(cc[mtl][nt], a0, a1, v8l[nt]);
                    mma8_bf16(cc[mtl][nt], b0, b1, v8h[nt]);
                }
            }
        }

        // ---- 3-stage tree reduce across warps (buffer: 4 x 32 x 33 floats) ----
        // stage 1: warps 4..7 -> regions 0..3; warps 0..3 add
        if (w >= 4) {
            float* reg = red1 + (w - 4) * 1056;
            #pragma unroll
            for (int mtl = 0; mtl < 2; mtl++)
                #pragma unroll
                for (int nt = 0; nt < 4; nt++)
                    #pragma unroll
                    for (int e = 0; e < 4; e++) {
                        int lr = mtl * 16 + gid + ((e >> 1) << 3);
                        int p = nt * 8 + tg * 2 + (e & 1);
                        reg[lr * 33 + p] = cc[mtl][nt][e];
                    }
        }
        __syncthreads();
        if (w < 4) {
            float* reg = red1 + w * 1056;
            #pragma unroll
            for (int mtl = 0; mtl < 2; mtl++)
                #pragma unroll
                for (int nt = 0; nt < 4; nt++)
                    #pragma unroll
                    for (int e = 0; e < 4; e++) {
                        int lr = mtl * 16 + gid + ((e >> 1) << 3);
                        int p = nt * 8 + tg * 2 + (e & 1);
                        cc[mtl][nt][e] += reg[lr * 33 + p];
                    }
        }
        __syncthreads();
        // stage 2: warps 2..3 -> regions 0..1; warps 0..1 add
        if (w == 2 || w == 3) {
            float* reg = red1 + (w - 2) * 1056;
            #pragma unroll
            for (int mtl = 0; mtl < 2; mtl++)
                #pragma unroll
                for (int nt = 0; nt < 4; nt++)
                    #pragma unroll
                    for (int e = 0; e < 4; e++) {
                        int lr = mtl * 16 + gid + ((e >> 1) << 3);
                        int p = nt * 8 + tg * 2 + (e & 1);
                        reg[lr * 33 + p] = cc[mtl][nt][e];
                    }
        }
        __syncthreads();
        if (w < 2) {
            float* reg = red1 + w * 1056;
            #pragma unroll
            for (int mtl = 0; mtl < 2; mtl++)
                #pragma unroll
                for (int nt = 0; nt < 4; nt++)
                    #pragma unroll
                    for (int e = 0; e < 4; e++) {
                        int lr = mtl * 16 + gid + ((e >> 1) << 3);
                        int p = nt * 8 + tg * 2 + (e & 1);
                        cc[mtl][nt][e] += reg[lr * 33 + p];
                    }
        }
        __syncthreads();
        // stage 3: warp 1 -> region 0; warp 0 adds + stores
        if (w == 1) {
            #pragma unroll
            for (int mtl = 0; mtl < 2; mtl++)
                #pragma unroll
                for (int nt = 0; nt < 4; nt++)
                    #pragma unroll
                    for (int e = 0; e < 4; e++) {
                        int lr = mtl * 16 + gid + ((e >> 1) << 3);
                        int p = nt * 8 + tg * 2 + (e & 1);
                        red1[lr * 33 + p] = cc[mtl][nt][e];
                    }
        }
        __syncthreads();
        if (w == 0) {
            #pragma unroll
            for (int mtl = 0; mtl < 2; mtl++)
                #pragma unroll
                for (int nt = 0; nt < 4; nt++)
                    #pragma unroll
                    for (int ee = 0; ee < 2; ee++) {
                        int lr = mtl * 16 + gid + ee * 8;
                        int row = mb + lr;
                        int p0 = nt * 8 + tg * 2;
                        float s0 = cc[mtl][nt][ee * 2]     + red1[lr * 33 + p0];
                        float s1 = cc[mtl][nt][ee * 2 + 1] + red1[lr * 33 + p0 + 1];
                        if (row < 49) {
                            size_t base = (size_t)(bxy * 49 + row) * 256 + h * 32 + p0;
                            __nv_bfloat16 h0 = __float2bfloat16_rn(s0);
                            __nv_bfloat16 h1 = __float2bfloat16_rn(s1);
                            *reinterpret_cast<__nv_bfloat162*>(g_AOh + base) =
                                __halves2bfloat162(h0, h1);
                            *reinterpret_cast<__nv_bfloat162*>(g_AOl + base) =
                                __halves2bfloat162(
                                    __float2bfloat16_rn(s0 - __bfloat162float(h0)),
                                    __float2bfloat16_rn(s1 - __bfloat162float(h1)));
                        }
                    }
        }
        __syncthreads();
    }
}

// ---------------- K4: final projection -----------------------------------------
__global__ void __launch_bounds__(256, 4) ao_mma(const int* __restrict__ mode,
                                                 const float* __restrict__ ba,
                                                 float* __restrict__ out) {
    extern __shared__ char sm[];
    int blk = blockIdx.x;
    int b = blk / 98; int r = blk - b * 98;
    int mt = r >> 1, nt = r & 1;
    int ta = mode[b * 6];
    const __nv_bfloat16* Ah = g_AOh + (size_t)(b * 3136 + mt * 64) * 256;
    const __nv_bfloat16* Al = g_AOl + (size_t)(b * 3136 + mt * 64) * 256;
    const __nv_bfloat16* Bh = g_WAh + (size_t)ta * 65536 + (size_t)nt * 128 * 256;
    const __nv_bfloat16* Bl = g_WAl + (size_t)ta * 65536 + (size_t)nt * 128 * 256;
    float acc[8][4] = {};
    gemm_tile(Ah, Al, Bh, Bl, acc, sm);

    int warp = threadIdx.x >> 5, lane = threadIdx.x & 31;
    int wm = warp >> 1, wn = warp & 1;
    int gid = lane >> 2, tg = lane & 3;
    #pragma unroll
    for (int j = 0; j < 8; j++) {
        #pragma unroll
        for (int ee = 0; ee < 2; ee++) {
            int row = mt * 64 + wm * 16 + gid + ee * 8;
            int o0 = nt * 128 + wn * 64 + j * 8 + tg * 2;
            float2 v;
            v.x = acc[j][ee * 2]     + ba[ta * 256 + o0];
            v.y = acc[j][ee * 2 + 1] + ba[ta * 256 + o0 + 1];
            *reinterpret_cast<float2*>(out + (size_t)(b * 3136 + row) * 256 + o0) = v;
        }
    }
}

// ---------------- launch --------------------------------------------------------
extern "C" void kernel_launch(void* const* d_in, const int* in_sizes, int n_in,
                              void* d_out, int out_size) {
    const float* x    = (const float*)d_in[0];
    const int*   mode = (const int*)  d_in[1];
    const float* Wq   = (const float*)d_in[2];
    const float* bq   = (const float*)d_in[3];
    const float* Wk   = (const float*)d_in[4];
    const float* bk   = (const float*)d_in[5];
    const float* Wv   = (const float*)d_in[6];
    const float* bv   = (const float*)d_in[7];
    const float* Wa   = (const float*)d_in[8];
    const float* ba   = (const float*)d_in[9];
    const float* ratt = (const float*)d_in[10];
    const float* rmsg = (const float*)d_in[11];
    const float* post = (const float*)d_in[12];
    float* out = (float*)d_out;

    cudaFuncSetAttribute(attn_kernel, cudaFuncAttributeMaxDynamicSharedMemorySize, SM_TOTAL);
    cudaFuncSetAttribute(proj_mma, cudaFuncAttributeMaxDynamicSharedMemorySize, 49152);
    cudaFuncSetAttribute(ao_mma,   cudaFuncAttributeMaxDynamicSharedMemorySize, 49152);

    pack_x    <<<18816, 256>>>(reinterpret_cast<const float4*>(x));
    pack_qa   <<<128, 256>>>(Wq, Wa);
    combine_w <<<192, 256>>>(Wk, bk, Wv, bv, ratt, rmsg, mode);
    proj_mma  <<<5096, 256, 49152>>>(mode, bq);
    attn_kernel<<<2048, 256, SM_TOTAL>>>(post);
    ao_mma    <<<392, 256, 49152>>>(mode, ba, out);
}